// round 14
// baseline (speedup 1.0000x reference)
#include <cuda_runtime.h>
#include <cuda_bf16.h>
#include <math.h>
#include <stdint.h>

// Problem constants
#define B_      1
#define S_      2048
#define H_      4096
#define NH_     32
#define NKV_    8
#define HD_     128
#define QKV_O   ((NH_ + 2 * NKV_) * HD_)   // 6144
#define Q_END   (NH_ * HD_)                // 4096
#define K_END   (Q_END + NKV_ * HD_)       // 5120
#define KVW_    (NKV_ * HD_)               // 1024

// ---------------------------------------------------------------------------
// Scratch (no allocations allowed)
// ---------------------------------------------------------------------------
__device__ __nv_bfloat16 g_hid_hi[S_ * H_];
__device__ __nv_bfloat16 g_hid_lo[S_ * H_];
__device__ __nv_bfloat16 g_wqkv_hi[QKV_O * H_];
__device__ __nv_bfloat16 g_wqkv_lo[QKV_O * H_];
__device__ __nv_bfloat16 g_wo_hi[H_ * H_];
__device__ __nv_bfloat16 g_wo_lo[H_ * H_];
__device__ __nv_bfloat16 g_attn_hi[S_ * H_];
__device__ __nv_bfloat16 g_attn_lo[S_ * H_];

__device__ __nv_bfloat16 g_q_hi[S_ * H_];            // RoPE'd Q  [2048, 4096]
__device__ __nv_bfloat16 g_q_lo[S_ * H_];
__device__ __nv_bfloat16 g_k_hi[S_ * KVW_];          // RoPE'd K  [2048, 1024]
__device__ __nv_bfloat16 g_k_lo[S_ * KVW_];
__device__ __nv_bfloat16 g_v_hi[S_ * KVW_];          // V         [2048, 1024]
__device__ __nv_bfloat16 g_v_lo[S_ * KVW_];

__device__ float g_cos[S_ * 64];
__device__ float g_sin[S_ * 64];
__device__ unsigned g_counters[4];      // work-stealing tile counters

// ---------------------------------------------------------------------------
// Baseline-ISA PTX helpers
// ---------------------------------------------------------------------------
__device__ __forceinline__ uint32_t smem_u32(const void* p) {
    uint32_t a;
    asm("{ .reg .u64 t; cvta.to.shared.u64 t, %1; cvt.u32.u64 %0, t; }"
        : "=r"(a) : "l"(p));
    return a;
}

#define CP_ASYNC16(dst, src) \
    asm volatile("cp.async.cg.shared.global [%0], [%1], 16;" \
        :: "r"(dst), "l"(src) : "memory")
#define CP_COMMIT() asm volatile("cp.async.commit_group;" ::: "memory")
#define CP_WAIT(n)  asm volatile("cp.async.wait_group %0;" :: "n"(n) : "memory")

#define LDSM_X4(r0, r1, r2, r3, addr) \
    asm volatile("ldmatrix.sync.aligned.m8n8.x4.shared.b16 {%0,%1,%2,%3}, [%4];" \
        : "=r"(r0), "=r"(r1), "=r"(r2), "=r"(r3) : "r"(addr))

#define LDSM_X4_T(r0, r1, r2, r3, addr) \
    asm volatile("ldmatrix.sync.aligned.m8n8.x4.trans.shared.b16 {%0,%1,%2,%3}, [%4];" \
        : "=r"(r0), "=r"(r1), "=r"(r2), "=r"(r3) : "r"(addr))

#define MMA_BF16(d, a, b0, b1) \
    asm volatile("mma.sync.aligned.m16n8k16.row.col.f32.bf16.bf16.f32 " \
        "{%0,%1,%2,%3}, {%4,%5,%6,%7}, {%8,%9}, {%0,%1,%2,%3};" \
        : "+f"((d)[0]), "+f"((d)[1]), "+f"((d)[2]), "+f"((d)[3]) \
        : "r"((a)[0]), "r"((a)[1]), "r"((a)[2]), "r"((a)[3]), "r"(b0), "r"(b1))

__device__ __forceinline__ uint32_t pack_bf16(float x, float y) {
    __nv_bfloat162 h = __floats2bfloat162_rn(x, y);
    return *(uint32_t*)&h;
}

// Packed tile swizzle for a 128-row x 64B tile (8KB)
__device__ __forceinline__ uint32_t tile_off(int row, int unit) {
    uint32_t off = (uint32_t)((row >> 1) * 128 + (row & 1) * 64 + unit * 16);
    return off ^ ((off >> 3) & 0x70);
}
// 256-row A tile: two 8KB subtiles
__device__ __forceinline__ uint32_t a_off(int row, int unit) {
    return (uint32_t)((row >> 7) * 8192) + tile_off(row & 127, unit);
}

// ---------------------------------------------------------------------------
// RoPE tables (double-precision sincos, computed once)
// ---------------------------------------------------------------------------
__global__ void rope_table_kernel(float* __restrict__ ct, float* __restrict__ st)
{
    int s = blockIdx.x;
    int d2 = threadIdx.x;     // 0..63
    double inv = exp(-((double)(2 * d2) / (double)HD_) * 9.210340371976184);
    double ang = (double)s * inv;
    double sv, cv;
    sincos(ang, &sv, &cv);
    ct[s * 64 + d2] = (float)cv;
    st[s * 64 + d2] = (float)sv;
}

// ---------------------------------------------------------------------------
// fp32 -> (bf16 hi, bf16 lo) split conversion.
// ---------------------------------------------------------------------------
__global__ void cvt_split_kernel(const float* __restrict__ x,
                                 __nv_bfloat16* __restrict__ hi,
                                 __nv_bfloat16* __restrict__ lo, int n4)
{
    int i = blockIdx.x * blockDim.x + threadIdx.x;
    if (i >= n4) return;
    float4 v = ((const float4*)x)[i];
    __nv_bfloat16 h0 = __float2bfloat16_rn(v.x);
    __nv_bfloat16 h1 = __float2bfloat16_rn(v.y);
    __nv_bfloat16 h2 = __float2bfloat16_rn(v.z);
    __nv_bfloat16 h3 = __float2bfloat16_rn(v.w);
    __nv_bfloat16 l0 = __float2bfloat16_rn(v.x - __bfloat162float(h0));
    __nv_bfloat16 l1 = __float2bfloat16_rn(v.y - __bfloat162float(h1));
    __nv_bfloat16 l2 = __float2bfloat16_rn(v.z - __bfloat162float(h2));
    __nv_bfloat16 l3 = __float2bfloat16_rn(v.w - __bfloat162float(h3));
    ((__nv_bfloat162*)hi)[i * 2 + 0] = __nv_bfloat162(h0, h1);
    ((__nv_bfloat162*)hi)[i * 2 + 1] = __nv_bfloat162(h2, h3);
    ((__nv_bfloat162*)lo)[i * 2 + 0] = __nv_bfloat162(l0, l1);
    ((__nv_bfloat162*)lo)[i * 2 + 1] = __nv_bfloat162(l2, l3);
}

// ---------------------------------------------------------------------------
// bf16x3 GEMM via mma.sync (HMMA):  C[M,N] = A[M,K] * B[N,K]^T
// CTA tile 256x128, 8 warps (4m x 2n), warp tile 64x64 (128B smem/MMA).
// 1 CTA/SM, 48KB stages x 3, single sync per chunk, persistent + stealing.
// qkv_mode: epilogue applies RoPE + hi/lo split.
// ---------------------------------------------------------------------------
#define A_TERM_B 16384              // 256 rows * 64B
#define B_TERM_B 8192               // 128 rows * 64B
#define STAGE_B  (2 * A_TERM_B + 2 * B_TERM_B)   // 49152
#define GEMM_STAGES 3
#define GEMM_SMEM_BYTES (GEMM_STAGES * STAGE_B)  // 147456
#define CT_PITCH 132                // fp32 stage pitch (256 rows -> 135KB, fits)

__global__ __launch_bounds__(256, 1) void gemm_mma_kernel(
    const __nv_bfloat16* __restrict__ Ahi, const __nv_bfloat16* __restrict__ Alo,
    const __nv_bfloat16* __restrict__ Bhi, const __nv_bfloat16* __restrict__ Blo,
    float* __restrict__ C, int N, int K, int Mtiles, int total_tiles,
    unsigned* __restrict__ counter, int qkv_mode,
    const float* __restrict__ ct, const float* __restrict__ st,
    __nv_bfloat16* __restrict__ qhi, __nv_bfloat16* __restrict__ qlo,
    __nv_bfloat16* __restrict__ khi, __nv_bfloat16* __restrict__ klo,
    __nv_bfloat16* __restrict__ vhi, __nv_bfloat16* __restrict__ vlo)
{
    extern __shared__ __align__(128) char smem[];
    __shared__ unsigned s_tile;
    const uint32_t sbase = smem_u32(smem);
    const int tid = threadIdx.x;
    const int wid = tid >> 5;
    const int lane = tid & 31;
    const int NC = K / 32;

    const int warp_m = wid & 3;      // 0..3 -> 64 rows each
    const int warp_n = wid >> 2;     // 0..1 -> 64 cols each
    const int q = lane >> 3;
    const int r = lane & 7;
    const int gp = lane >> 2;
    const int tg = lane & 3;

    for (;;) {
        if (tid == 0) s_tile = atomicAdd(counter, 1u);
        __syncthreads();                 // tile uniform + prev epilogue done
        const unsigned t = s_tile;
        if (t >= (unsigned)total_tiles) return;
        const int m0 = ((int)t % Mtiles) * 256;
        const int n0 = ((int)t / Mtiles) * 128;

        float acc[4][8][4];
#pragma unroll
        for (int mt = 0; mt < 4; mt++)
#pragma unroll
            for (int nt = 0; nt < 8; nt++)
#pragma unroll
                for (int e = 0; e < 4; e++) acc[mt][nt][e] = 0.0f;

        auto load_stage = [&](int stage, int c) {
            const uint32_t st_ = sbase + (uint32_t)stage * STAGE_B;
            // A: 2 terms x 256 rows x 4 units = 2048 chunks
#pragma unroll
            for (int i = 0; i < 8; i++) {
                int g = tid + i * 256;
                int term = g >> 10;
                int rem = g & 1023;
                int row = rem >> 2;
                int u = rem & 3;
                const __nv_bfloat16* src = (term ? Alo : Ahi)
                    + (size_t)(m0 + row) * K + c * 32 + u * 8;
                CP_ASYNC16(st_ + (uint32_t)term * A_TERM_B + a_off(row, u), src);
            }
            // B: 2 terms x 128 rows x 4 units = 1024 chunks
#pragma unroll
            for (int i = 0; i < 4; i++) {
                int g = tid + i * 256;
                int term = g >> 9;
                int rem = g & 511;
                int row = rem >> 2;
                int u = rem & 3;
                const __nv_bfloat16* src = (term ? Blo : Bhi)
                    + (size_t)(n0 + row) * K + c * 32 + u * 8;
                CP_ASYNC16(st_ + 2 * A_TERM_B + (uint32_t)term * B_TERM_B
                           + tile_off(row, u), src);
            }
            CP_COMMIT();
        };

        load_stage(0, 0);
        load_stage(1, 1);

        int stage = 0;
        for (int c = 0; c < NC; c++) {
            if (c + 1 < NC) { CP_WAIT(1); }
            else           { CP_WAIT(0); }
            __syncthreads();
            if (c + 2 < NC) load_stage((stage + 2) % GEMM_STAGES, c + 2);

            const uint32_t st_ = sbase + (uint32_t)stage * STAGE_B;
            const uint32_t aBase = st_;
            const uint32_t bBase = st_ + 2 * A_TERM_B;

#pragma unroll
            for (int kstep = 0; kstep < 2; kstep++) {
                // B fragments: 4 pr-blocks x (hi,lo)
                uint32_t bh[4][4], bl[4][4];
                const int bunit = kstep * 2 + (q & 1);
#pragma unroll
                for (int pr = 0; pr < 4; pr++) {
                    int brow = warp_n * 64 + pr * 16 + (q >> 1) * 8 + r;
                    uint32_t a0 = bBase + tile_off(brow, bunit);
                    LDSM_X4(bh[pr][0], bh[pr][1], bh[pr][2], bh[pr][3], a0);
                    LDSM_X4(bl[pr][0], bl[pr][1], bl[pr][2], bl[pr][3], a0 + B_TERM_B);
                }
                const int aunit = kstep * 2 + (q >> 1);
                const int abase_row = warp_m * 64 + (q & 1) * 8 + r;

                uint32_t ahA[4], alA[4], ahB[4], alB[4];
                {
                    uint32_t addr = aBase + a_off(abase_row, aunit);
                    LDSM_X4(ahA[0], ahA[1], ahA[2], ahA[3], addr);
                    LDSM_X4(alA[0], alA[1], alA[2], alA[3], addr + A_TERM_B);
                }
#pragma unroll
                for (int mt = 0; mt < 4; mt++) {
                    uint32_t* ah = (mt & 1) ? ahB : ahA;
                    uint32_t* al = (mt & 1) ? alB : alA;
                    if (mt < 3) {
                        uint32_t* nh = (mt & 1) ? ahA : ahB;
                        uint32_t* nl = (mt & 1) ? alA : alB;
                        uint32_t addr = aBase + a_off(abase_row + (mt + 1) * 16, aunit);
                        LDSM_X4(nh[0], nh[1], nh[2], nh[3], addr);
                        LDSM_X4(nl[0], nl[1], nl[2], nl[3], addr + A_TERM_B);
                    }
#pragma unroll
                    for (int pr = 0; pr < 4; pr++) {
                        MMA_BF16(acc[mt][2 * pr],     ah, bh[pr][0], bh[pr][1]);
                        MMA_BF16(acc[mt][2 * pr + 1], ah, bh[pr][2], bh[pr][3]);
                    }
#pragma unroll
                    for (int pr = 0; pr < 4; pr++) {
                        MMA_BF16(acc[mt][2 * pr],     ah, bl[pr][0], bl[pr][1]);
                        MMA_BF16(acc[mt][2 * pr + 1], ah, bl[pr][2], bl[pr][3]);
                    }
#pragma unroll
                    for (int pr = 0; pr < 4; pr++) {
                        MMA_BF16(acc[mt][2 * pr],     al, bh[pr][0], bh[pr][1]);
                        MMA_BF16(acc[mt][2 * pr + 1], al, bh[pr][2], bh[pr][3]);
                    }
                }
            }
            stage = (stage + 1) % GEMM_STAGES;
        }

        // ------------------------ Epilogue ------------------------
        if (!qkv_mode) {
#pragma unroll
            for (int mt = 0; mt < 4; mt++) {
#pragma unroll
                for (int nt = 0; nt < 8; nt++) {
                    int row = m0 + warp_m * 64 + mt * 16 + gp;
                    int col = n0 + warp_n * 64 + nt * 8 + tg * 2;
                    *(float2*)&C[(size_t)row * N + col] =
                        make_float2(acc[mt][nt][0], acc[mt][nt][1]);
                    *(float2*)&C[(size_t)(row + 8) * N + col] =
                        make_float2(acc[mt][nt][2], acc[mt][nt][3]);
                }
            }
        } else if (n0 >= K_END) {
            // V tile: straight hi/lo split from registers
            int colbase = n0 - K_END;
#pragma unroll
            for (int mt = 0; mt < 4; mt++) {
#pragma unroll
                for (int nt = 0; nt < 8; nt++) {
                    int r0 = m0 + warp_m * 64 + mt * 16 + gp;
                    int cc = colbase + warp_n * 64 + nt * 8 + tg * 2;
#pragma unroll
                    for (int hf = 0; hf < 2; hf++) {
                        float o0 = acc[mt][nt][2 * hf];
                        float o1 = acc[mt][nt][2 * hf + 1];
                        float h0 = __bfloat162float(__float2bfloat16_rn(o0));
                        float h1 = __bfloat162float(__float2bfloat16_rn(o1));
                        size_t off = (size_t)(r0 + hf * 8) * KVW_ + cc;
                        *(uint32_t*)(vhi + off) = pack_bf16(h0, h1);
                        *(uint32_t*)(vlo + off) = pack_bf16(o0 - h0, o1 - h1);
                    }
                }
            }
        } else {
            // Q or K tile: stage fp32 tile (256 x 128) to smem, rope, split
            __syncthreads();
            float* ctile = (float*)smem;
#pragma unroll
            for (int mt = 0; mt < 4; mt++) {
#pragma unroll
                for (int nt = 0; nt < 8; nt++) {
                    int r0 = warp_m * 64 + mt * 16 + gp;
                    int cc = warp_n * 64 + nt * 8 + tg * 2;
                    ctile[r0 * CT_PITCH + cc] = acc[mt][nt][0];
                    ctile[r0 * CT_PITCH + cc + 1] = acc[mt][nt][1];
                    ctile[(r0 + 8) * CT_PITCH + cc] = acc[mt][nt][2];
                    ctile[(r0 + 8) * CT_PITCH + cc + 1] = acc[mt][nt][3];
                }
            }
            __syncthreads();

            __nv_bfloat16 *dhi, *dlo;
            int width, colbase;
            if (n0 < Q_END) { dhi = qhi; dlo = qlo; width = H_;   colbase = n0; }
            else            { dhi = khi; dlo = klo; width = KVW_; colbase = n0 - Q_END; }

            // 256 rows x 32 pairs = 8192 work items / 256 threads
#pragma unroll
            for (int it = 0; it < 32; it++) {
                int g = tid + it * 256;
                int row = g >> 5;
                int d2 = (g & 31) * 2;
                float2 x1 = *(float2*)&ctile[row * CT_PITCH + d2];
                float2 x2 = *(float2*)&ctile[row * CT_PITCH + 64 + d2];
                int s = m0 + row;
                float2 cv = *(const float2*)&ct[s * 64 + d2];
                float2 sv = *(const float2*)&st[s * 64 + d2];
                float y1a = x1.x * cv.x - x2.x * sv.x;
                float y1b = x1.y * cv.y - x2.y * sv.y;
                float y2a = x1.x * sv.x + x2.x * cv.x;
                float y2b = x1.y * sv.y + x2.y * cv.y;

                float h1a = __bfloat162float(__float2bfloat16_rn(y1a));
                float h1b = __bfloat162float(__float2bfloat16_rn(y1b));
                float h2a = __bfloat162float(__float2bfloat16_rn(y2a));
                float h2b = __bfloat162float(__float2bfloat16_rn(y2b));

                size_t ob = (size_t)s * width + colbase + d2;
                *(uint32_t*)(dhi + ob)      = pack_bf16(h1a, h1b);
                *(uint32_t*)(dlo + ob)      = pack_bf16(y1a - h1a, y1b - h1b);
                *(uint32_t*)(dhi + ob + 64) = pack_bf16(h2a, h2b);
                *(uint32_t*)(dlo + ob + 64) = pack_bf16(y2a - h2a, y2b - h2b);
            }
        }
    }
}

// ---------------------------------------------------------------------------
// Flash attention via mma.sync, bf16x3 QK^T and bf16x3 PV, causal, GQA.
// BQ=64 (4 warps), 2 CTA/SM, persistent + work-stealing (R12 config).
// ---------------------------------------------------------------------------
#define AP_ 136
#define APB_ 272
#define Q_COMP_B 17408
#define KV_COMP_B 8704
#define KV_STAGE_B (4 * KV_COMP_B)
#define ATTN_SMEM_BYTES (2 * Q_COMP_B + 2 * KV_STAGE_B)   // 104448

__global__ __launch_bounds__(128, 2) void flash_attn_mma_kernel(
    const __nv_bfloat16* __restrict__ qhi, const __nv_bfloat16* __restrict__ qlo,
    const __nv_bfloat16* __restrict__ khi, const __nv_bfloat16* __restrict__ klo,
    const __nv_bfloat16* __restrict__ vhi, const __nv_bfloat16* __restrict__ vlo,
    __nv_bfloat16* __restrict__ out_hi, __nv_bfloat16* __restrict__ out_lo,
    int total_tiles, unsigned* __restrict__ counter)
{
    extern __shared__ __align__(128) char smA[];
    __shared__ unsigned s_tile;
    const uint32_t sb = smem_u32(smA);
    const int tid = threadIdx.x;
    const int wid = tid >> 5;
    const int lane = tid & 31;
    const int gp = lane >> 2;
    const int tg = lane & 3;

    const uint32_t Qhi_s = sb;
    const uint32_t Qlo_s = sb + Q_COMP_B;
    const uint32_t Stage_s = sb + 2 * Q_COMP_B;
    const float scale = 0.08838834764831845f;

    for (;;) {
        if (tid == 0) s_tile = atomicAdd(counter, 1u);
        __syncthreads();
        const unsigned t = s_tile;
        if (t >= (unsigned)total_tiles) return;
        const int qb = (S_ / 64 - 1) - (int)(t >> 5);  // heavy first
        const int head = (int)(t & 31);
        const int kvh = head >> 2;
        const int q0 = qb * 64;

#pragma unroll
        for (int i = 0; i < 16; i++) {
            int g = tid + i * 128;
            int comp = g >> 10;
            int rem = g & 1023;
            int row = rem >> 4;
            int u = rem & 15;
            const __nv_bfloat16* src = (comp ? qlo : qhi)
                + (size_t)(q0 + row) * H_ + head * HD_ + u * 8;
            uint32_t dst = (comp ? Qlo_s : Qhi_s) + (uint32_t)(row * APB_ + u * 16);
            CP_ASYNC16(dst, src);
        }
        CP_COMMIT();

        const int kb_max = 2 * qb + 1;

        auto load_kv = [&](int stage, int kb) {
            uint32_t st = Stage_s + (uint32_t)stage * KV_STAGE_B;
            const __nv_bfloat16* bases[4] = {khi, klo, vhi, vlo};
#pragma unroll
            for (int i = 0; i < 16; i++) {
                int g = tid + i * 128;
                int comp = g >> 9;
                int rem = g & 511;
                int row = rem >> 4;
                int u = rem & 15;
                const __nv_bfloat16* src = bases[comp]
                    + (size_t)(kb * 32 + row) * KVW_ + kvh * HD_ + u * 8;
                CP_ASYNC16(st + (uint32_t)(comp * KV_COMP_B + row * APB_ + u * 16), src);
            }
            CP_COMMIT();
        };

        load_kv(0, 0);

        float O[16][4];
        float m_i[2] = {-1e30f, -1e30f};
        float l_i[2] = {0.0f, 0.0f};
#pragma unroll
        for (int nt = 0; nt < 16; nt++)
#pragma unroll
            for (int e = 0; e < 4; e++) O[nt][e] = 0.0f;

        for (int kb = 0; kb <= kb_max; kb++) {
            if (kb < kb_max) { load_kv((kb + 1) & 1, kb + 1); CP_WAIT(1); }
            else             { CP_WAIT(0); }
            __syncthreads();

            const uint32_t st = Stage_s + (uint32_t)(kb & 1) * KV_STAGE_B;
            const uint32_t Ks_hi = st;
            const uint32_t Ks_lo = st + KV_COMP_B;
            const uint32_t Vs_hi = st + 2 * KV_COMP_B;
            const uint32_t Vs_lo = st + 3 * KV_COMP_B;

            float S[4][4];
#pragma unroll
            for (int tt = 0; tt < 4; tt++)
#pragma unroll
                for (int e = 0; e < 4; e++) S[tt][e] = 0.0f;

#pragma unroll
            for (int kt = 0; kt < 8; kt++) {
                uint32_t aoff = (uint32_t)((wid * 16 + (lane & 15)) * APB_
                                           + (kt * 16 + (lane >> 4) * 8) * 2);
                uint32_t ahi[4], alo[4];
                LDSM_X4(ahi[0], ahi[1], ahi[2], ahi[3], Qhi_s + aoff);
                LDSM_X4(alo[0], alo[1], alo[2], alo[3], Qlo_s + aoff);

                uint32_t bh[2][4], bl[2][4];
#pragma unroll
                for (int pr = 0; pr < 2; pr++) {
                    uint32_t boff = (uint32_t)((pr * 16 + (lane >> 4) * 8 + (lane & 7)) * APB_
                                               + (kt * 16 + ((lane >> 3) & 1) * 8) * 2);
                    LDSM_X4(bh[pr][0], bh[pr][1], bh[pr][2], bh[pr][3], Ks_hi + boff);
                    LDSM_X4(bl[pr][0], bl[pr][1], bl[pr][2], bl[pr][3], Ks_lo + boff);
                }
                MMA_BF16(S[0], ahi, bh[0][0], bh[0][1]);
                MMA_BF16(S[1], ahi, bh[0][2], bh[0][3]);
                MMA_BF16(S[2], ahi, bh[1][0], bh[1][1]);
                MMA_BF16(S[3], ahi, bh[1][2], bh[1][3]);

                MMA_BF16(S[0], ahi, bl[0][0], bl[0][1]);
                MMA_BF16(S[1], ahi, bl[0][2], bl[0][3]);
                MMA_BF16(S[2], ahi, bl[1][0], bl[1][1]);
                MMA_BF16(S[3], ahi, bl[1][2], bl[1][3]);

                MMA_BF16(S[0], alo, bh[0][0], bh[0][1]);
                MMA_BF16(S[1], alo, bh[0][2], bh[0][3]);
                MMA_BF16(S[2], alo, bh[1][0], bh[1][1]);
                MMA_BF16(S[3], alo, bh[1][2], bh[1][3]);
            }

            if (kb >= 2 * qb) {
#pragma unroll
                for (int tt = 0; tt < 4; tt++) {
                    int colb = kb * 32 + tt * 8 + 2 * tg;
#pragma unroll
                    for (int e = 0; e < 4; e++) {
                        int col = colb + (e & 1);
                        int row = q0 + wid * 16 + gp + ((e >= 2) ? 8 : 0);
                        S[tt][e] = (col <= row) ? S[tt][e] * scale : -1e30f;
                    }
                }
            } else {
#pragma unroll
                for (int tt = 0; tt < 4; tt++)
#pragma unroll
                    for (int e = 0; e < 4; e++) S[tt][e] *= scale;
            }

#pragma unroll
            for (int h = 0; h < 2; h++) {
                float mx = -1e30f;
#pragma unroll
                for (int tt = 0; tt < 4; tt++)
                    mx = fmaxf(mx, fmaxf(S[tt][2 * h], S[tt][2 * h + 1]));
                mx = fmaxf(mx, __shfl_xor_sync(0xffffffffu, mx, 1));
                mx = fmaxf(mx, __shfl_xor_sync(0xffffffffu, mx, 2));
                float m_new = fmaxf(m_i[h], mx);
                float alpha = __expf(m_i[h] - m_new);
                float sum = 0.0f;
#pragma unroll
                for (int tt = 0; tt < 4; tt++) {
                    S[tt][2 * h]     = __expf(S[tt][2 * h] - m_new);
                    S[tt][2 * h + 1] = __expf(S[tt][2 * h + 1] - m_new);
                    sum += S[tt][2 * h] + S[tt][2 * h + 1];
                }
                sum += __shfl_xor_sync(0xffffffffu, sum, 1);
                sum += __shfl_xor_sync(0xffffffffu, sum, 2);
                l_i[h] = l_i[h] * alpha + sum;
                m_i[h] = m_new;
#pragma unroll
                for (int nt = 0; nt < 16; nt++) {
                    O[nt][2 * h] *= alpha;
                    O[nt][2 * h + 1] *= alpha;
                }
            }

#pragma unroll
            for (int kt2 = 0; kt2 < 2; kt2++) {
                uint32_t phi[4], plo[4];
                {
                    float* p0 = S[2 * kt2];
                    float* p1 = S[2 * kt2 + 1];
                    float h00 = __bfloat162float(__float2bfloat16_rn(p0[0]));
                    float h01 = __bfloat162float(__float2bfloat16_rn(p0[1]));
                    float h02 = __bfloat162float(__float2bfloat16_rn(p0[2]));
                    float h03 = __bfloat162float(__float2bfloat16_rn(p0[3]));
                    float h10 = __bfloat162float(__float2bfloat16_rn(p1[0]));
                    float h11 = __bfloat162float(__float2bfloat16_rn(p1[1]));
                    float h12 = __bfloat162float(__float2bfloat16_rn(p1[2]));
                    float h13 = __bfloat162float(__float2bfloat16_rn(p1[3]));
                    phi[0] = pack_bf16(h00, h01);
                    phi[1] = pack_bf16(h02, h03);
                    phi[2] = pack_bf16(h10, h11);
                    phi[3] = pack_bf16(h12, h13);
                    plo[0] = pack_bf16(p0[0] - h00, p0[1] - h01);
                    plo[1] = pack_bf16(p0[2] - h02, p0[3] - h03);
                    plo[2] = pack_bf16(p1[0] - h10, p1[1] - h11);
                    plo[3] = pack_bf16(p1[2] - h12, p1[3] - h13);
                }
#pragma unroll
                for (int dq = 0; dq < 4; dq++) {
                    uint32_t bh0[4], bl0[4], bh1[4], bl1[4];
#pragma unroll
                    for (int half = 0; half < 2; half++) {
                        int dp = 2 * dq + half;
                        uint32_t voff = (uint32_t)((kt2 * 16 + ((lane >> 3) & 1) * 8 + (lane & 7)) * APB_
                                                   + (dp * 16 + (lane >> 4) * 8) * 2);
                        if (half == 0) {
                            LDSM_X4_T(bh0[0], bh0[1], bh0[2], bh0[3], Vs_hi + voff);
                            LDSM_X4_T(bl0[0], bl0[1], bl0[2], bl0[3], Vs_lo + voff);
                        } else {
                            LDSM_X4_T(bh1[0], bh1[1], bh1[2], bh1[3], Vs_hi + voff);
                            LDSM_X4_T(bl1[0], bl1[1], bl1[2], bl1[3], Vs_lo + voff);
                        }
                    }
                    float* O0 = O[4 * dq + 0];
                    float* O1 = O[4 * dq + 1];
                    float* O2 = O[4 * dq + 2];
                    float* O3 = O[4 * dq + 3];
                    MMA_BF16(O0, phi, bh0[0], bh0[1]);
                    MMA_BF16(O1, phi, bh0[2], bh0[3]);
                    MMA_BF16(O2, phi, bh1[0], bh1[1]);
                    MMA_BF16(O3, phi, bh1[2], bh1[3]);

                    MMA_BF16(O0, phi, bl0[0], bl0[1]);
                    MMA_BF16(O1, phi, bl0[2], bl0[3]);
                    MMA_BF16(O2, phi, bl1[0], bl1[1]);
                    MMA_BF16(O3, phi, bl1[2], bl1[3]);

                    MMA_BF16(O0, plo, bh0[0], bh0[1]);
                    MMA_BF16(O1, plo, bh0[2], bh0[3]);
                    MMA_BF16(O2, plo, bh1[0], bh1[1]);
                    MMA_BF16(O3, plo, bh1[2], bh1[3]);
                }
            }
            __syncthreads();
        }

#pragma unroll
        for (int h = 0; h < 2; h++) {
            float inv = 1.0f / l_i[h];
            int row = q0 + wid * 16 + gp + h * 8;
            size_t base = (size_t)row * H_ + head * HD_;
#pragma unroll
            for (int nt = 0; nt < 16; nt++) {
                float o0 = O[nt][2 * h] * inv;
                float o1 = O[nt][2 * h + 1] * inv;
                float hh0 = __bfloat162float(__float2bfloat16_rn(o0));
                float hh1 = __bfloat162float(__float2bfloat16_rn(o1));
                size_t off = base + nt * 8 + 2 * tg;
                *(uint32_t*)(out_hi + off) = pack_bf16(hh0, hh1);
                *(uint32_t*)(out_lo + off) = pack_bf16(o0 - hh0, o1 - hh1);
            }
        }
    }
}

// ---------------------------------------------------------------------------
extern "C" void kernel_launch(void* const* d_in, const int* in_sizes, int n_in,
                              void* d_out, int out_size)
{
    const float* hidden = (const float*)d_in[0];   // [1,2048,4096]
    const float* Wqkv   = (const float*)d_in[1];   // [6144,4096]
    const float* Wo     = (const float*)d_in[2];   // [4096,4096]
    float* out = (float*)d_out;                    // [1,2048,4096]

    __nv_bfloat16 *hid_hi, *hid_lo, *wqkv_hi, *wqkv_lo, *wo_hi, *wo_lo, *attn_hi, *attn_lo;
    __nv_bfloat16 *q_hi, *q_lo, *k_hi, *k_lo, *v_hi, *v_lo;
    float *ct, *st;
    unsigned* counters;
    cudaGetSymbolAddress((void**)&hid_hi, g_hid_hi);
    cudaGetSymbolAddress((void**)&hid_lo, g_hid_lo);
    cudaGetSymbolAddress((void**)&wqkv_hi, g_wqkv_hi);
    cudaGetSymbolAddress((void**)&wqkv_lo, g_wqkv_lo);
    cudaGetSymbolAddress((void**)&wo_hi, g_wo_hi);
    cudaGetSymbolAddress((void**)&wo_lo, g_wo_lo);
    cudaGetSymbolAddress((void**)&attn_hi, g_attn_hi);
    cudaGetSymbolAddress((void**)&attn_lo, g_attn_lo);
    cudaGetSymbolAddress((void**)&q_hi, g_q_hi);
    cudaGetSymbolAddress((void**)&q_lo, g_q_lo);
    cudaGetSymbolAddress((void**)&k_hi, g_k_hi);
    cudaGetSymbolAddress((void**)&k_lo, g_k_lo);
    cudaGetSymbolAddress((void**)&v_hi, g_v_hi);
    cudaGetSymbolAddress((void**)&v_lo, g_v_lo);
    cudaGetSymbolAddress((void**)&ct, g_cos);
    cudaGetSymbolAddress((void**)&st, g_sin);
    cudaGetSymbolAddress((void**)&counters, g_counters);

    int smCount = 148;
    cudaDeviceGetAttribute(&smCount, cudaDevAttrMultiProcessorCount, 0);
    const int gemm_grid = smCount;       // 1 CTA/SM
    const int attn_grid = 2 * smCount;

    cudaFuncSetAttribute(gemm_mma_kernel,
                         cudaFuncAttributeMaxDynamicSharedMemorySize, GEMM_SMEM_BYTES);
    cudaFuncSetAttribute(flash_attn_mma_kernel,
                         cudaFuncAttributeMaxDynamicSharedMemorySize, ATTN_SMEM_BYTES);

    // reset counters; rope tables
    cudaMemsetAsync(counters, 0, 4 * sizeof(unsigned));
    rope_table_kernel<<<S_, 64>>>(ct, st);

    // 0) split-convert inputs
    {
        int n4;
        n4 = (S_ * H_) / 4;
        cvt_split_kernel<<<(n4 + 255) / 256, 256>>>(hidden, hid_hi, hid_lo, n4);
        n4 = (QKV_O * H_) / 4;
        cvt_split_kernel<<<(n4 + 255) / 256, 256>>>(Wqkv, wqkv_hi, wqkv_lo, n4);
        n4 = (H_ * H_) / 4;
        cvt_split_kernel<<<(n4 + 255) / 256, 256>>>(Wo, wo_hi, wo_lo, n4);
    }

    // 1) QKV projection, fused RoPE + split epilogue (256x128 tiles)
    {
        int mt = S_ / 256, nt = QKV_O / 128;   // 8 x 48 = 384 tiles
        gemm_mma_kernel<<<gemm_grid, 256, GEMM_SMEM_BYTES>>>(
            hid_hi, hid_lo, wqkv_hi, wqkv_lo, nullptr, QKV_O, H_, mt, mt * nt,
            counters + 0, 1, ct, st,
            q_hi, q_lo, k_hi, k_lo, v_hi, v_lo);
    }

    // 2) Flash attention (BQ=64, 2 CTA/SM, persistent + work-stealing)
    {
        int tiles = (S_ / 64) * NH_;   // 1024
        flash_attn_mma_kernel<<<attn_grid, 128, ATTN_SMEM_BYTES>>>(
            q_hi, q_lo, k_hi, k_lo, v_hi, v_lo, attn_hi, attn_lo,
            tiles, counters + 1);
    }

    // 3) Output projection (plain fp32 epilogue, 256x128 tiles)
    {
        int mt = S_ / 256, nt = H_ / 128;      // 8 x 32 = 256 tiles
        gemm_mma_kernel<<<gemm_grid, 256, GEMM_SMEM_BYTES>>>(
            attn_hi, attn_lo, wo_hi, wo_lo, out, H_, H_, mt, mt * nt,
            counters + 2, 0, ct, st,
            nullptr, nullptr, nullptr, nullptr, nullptr, nullptr);
    }
}

// round 15
// speedup vs baseline: 1.0959x; 1.0959x over previous
#include <cuda_runtime.h>
#include <cuda_bf16.h>
#include <math.h>
#include <stdint.h>

// Problem constants
#define B_      1
#define S_      2048
#define H_      4096
#define NH_     32
#define NKV_    8
#define HD_     128
#define QKV_O   ((NH_ + 2 * NKV_) * HD_)   // 6144
#define Q_END   (NH_ * HD_)                // 4096
#define K_END   (Q_END + NKV_ * HD_)       // 5120
#define KVW_    (NKV_ * HD_)               // 1024

// ---------------------------------------------------------------------------
// Scratch (no allocations allowed)
// ---------------------------------------------------------------------------
__device__ __nv_bfloat16 g_hid_hi[S_ * H_];
__device__ __nv_bfloat16 g_hid_lo[S_ * H_];
__device__ __nv_bfloat16 g_wqkv_hi[QKV_O * H_];
__device__ __nv_bfloat16 g_wqkv_lo[QKV_O * H_];
__device__ __nv_bfloat16 g_wo_hi[H_ * H_];
__device__ __nv_bfloat16 g_wo_lo[H_ * H_];
__device__ __nv_bfloat16 g_attn_hi[S_ * H_];
__device__ __nv_bfloat16 g_attn_lo[S_ * H_];

__device__ __nv_bfloat16 g_q_hi[S_ * H_];            // RoPE'd Q  [2048, 4096]
__device__ __nv_bfloat16 g_q_lo[S_ * H_];
__device__ __nv_bfloat16 g_k_hi[S_ * KVW_];          // RoPE'd K  [2048, 1024]
__device__ __nv_bfloat16 g_k_lo[S_ * KVW_];
__device__ __nv_bfloat16 g_v_hi[S_ * KVW_];          // V         [2048, 1024]
__device__ __nv_bfloat16 g_v_lo[S_ * KVW_];

__device__ float g_cos[S_ * 64];
__device__ float g_sin[S_ * 64];
__device__ unsigned g_counters[4];      // work-stealing tile counters

// ---------------------------------------------------------------------------
// Baseline-ISA PTX helpers
// ---------------------------------------------------------------------------
__device__ __forceinline__ uint32_t smem_u32(const void* p) {
    uint32_t a;
    asm("{ .reg .u64 t; cvta.to.shared.u64 t, %1; cvt.u32.u64 %0, t; }"
        : "=r"(a) : "l"(p));
    return a;
}

#define CP_ASYNC16(dst, src) \
    asm volatile("cp.async.cg.shared.global [%0], [%1], 16;" \
        :: "r"(dst), "l"(src) : "memory")
#define CP_COMMIT() asm volatile("cp.async.commit_group;" ::: "memory")
#define CP_WAIT(n)  asm volatile("cp.async.wait_group %0;" :: "n"(n) : "memory")

#define LDSM_X4(r0, r1, r2, r3, addr) \
    asm volatile("ldmatrix.sync.aligned.m8n8.x4.shared.b16 {%0,%1,%2,%3}, [%4];" \
        : "=r"(r0), "=r"(r1), "=r"(r2), "=r"(r3) : "r"(addr))

#define LDSM_X4_T(r0, r1, r2, r3, addr) \
    asm volatile("ldmatrix.sync.aligned.m8n8.x4.trans.shared.b16 {%0,%1,%2,%3}, [%4];" \
        : "=r"(r0), "=r"(r1), "=r"(r2), "=r"(r3) : "r"(addr))

#define MMA_BF16(d, a, b0, b1) \
    asm volatile("mma.sync.aligned.m16n8k16.row.col.f32.bf16.bf16.f32 " \
        "{%0,%1,%2,%3}, {%4,%5,%6,%7}, {%8,%9}, {%0,%1,%2,%3};" \
        : "+f"((d)[0]), "+f"((d)[1]), "+f"((d)[2]), "+f"((d)[3]) \
        : "r"((a)[0]), "r"((a)[1]), "r"((a)[2]), "r"((a)[3]), "r"(b0), "r"(b1))

__device__ __forceinline__ uint32_t pack_bf16(float x, float y) {
    __nv_bfloat162 h = __floats2bfloat162_rn(x, y);
    return *(uint32_t*)&h;
}

// Packed tile swizzle (conflict-free for cp.async stores + ldmatrix phases)
__device__ __forceinline__ uint32_t tile_off(int row, int unit) {
    uint32_t off = (uint32_t)((row >> 1) * 128 + (row & 1) * 64 + unit * 16);
    return off ^ ((off >> 3) & 0x70);
}

// ---------------------------------------------------------------------------
// RoPE tables (double-precision sincos, computed once)
// ---------------------------------------------------------------------------
__global__ void rope_table_kernel(float* __restrict__ ct, float* __restrict__ st)
{
    int s = blockIdx.x;
    int d2 = threadIdx.x;     // 0..63
    double inv = exp(-((double)(2 * d2) / (double)HD_) * 9.210340371976184);
    double ang = (double)s * inv;
    double sv, cv;
    sincos(ang, &sv, &cv);
    ct[s * 64 + d2] = (float)cv;
    st[s * 64 + d2] = (float)sv;
}

// ---------------------------------------------------------------------------
// Fused fp32 -> (bf16 hi, bf16 lo) split for all three inputs, one launch.
// ---------------------------------------------------------------------------
#define N4_HID  (S_ * H_ / 4)              // 2097152
#define N4_WQKV (QKV_O * H_ / 4)           // 6291456
#define N4_WO   (H_ * H_ / 4)              // 4194304
#define N4_ALL  (N4_HID + N4_WQKV + N4_WO) // 12582912

__global__ void cvt_all_kernel(
    const float* __restrict__ hid, const float* __restrict__ wqkv,
    const float* __restrict__ wo,
    __nv_bfloat16* __restrict__ hid_hi, __nv_bfloat16* __restrict__ hid_lo,
    __nv_bfloat16* __restrict__ wqkv_hi, __nv_bfloat16* __restrict__ wqkv_lo,
    __nv_bfloat16* __restrict__ wo_hi, __nv_bfloat16* __restrict__ wo_lo)
{
    int i = blockIdx.x * blockDim.x + threadIdx.x;
    if (i >= N4_ALL) return;
    const float* src;
    __nv_bfloat16 *hi, *lo;
    int j;
    if (i < N4_HID)                { src = hid;  hi = hid_hi;  lo = hid_lo;  j = i; }
    else if (i < N4_HID + N4_WQKV) { src = wqkv; hi = wqkv_hi; lo = wqkv_lo; j = i - N4_HID; }
    else                           { src = wo;   hi = wo_hi;   lo = wo_lo;   j = i - N4_HID - N4_WQKV; }

    float4 v = ((const float4*)src)[j];
    __nv_bfloat16 h0 = __float2bfloat16_rn(v.x);
    __nv_bfloat16 h1 = __float2bfloat16_rn(v.y);
    __nv_bfloat16 h2 = __float2bfloat16_rn(v.z);
    __nv_bfloat16 h3 = __float2bfloat16_rn(v.w);
    __nv_bfloat16 l0 = __float2bfloat16_rn(v.x - __bfloat162float(h0));
    __nv_bfloat16 l1 = __float2bfloat16_rn(v.y - __bfloat162float(h1));
    __nv_bfloat16 l2 = __float2bfloat16_rn(v.z - __bfloat162float(h2));
    __nv_bfloat16 l3 = __float2bfloat16_rn(v.w - __bfloat162float(h3));
    ((__nv_bfloat162*)hi)[j * 2 + 0] = __nv_bfloat162(h0, h1);
    ((__nv_bfloat162*)hi)[j * 2 + 1] = __nv_bfloat162(h2, h3);
    ((__nv_bfloat162*)lo)[j * 2 + 0] = __nv_bfloat162(l0, l1);
    ((__nv_bfloat162*)lo)[j * 2 + 1] = __nv_bfloat162(l2, l3);
}

// ---------------------------------------------------------------------------
// bf16x3 GEMM via mma.sync (HMMA):  C[M,N] = A[M,K] * B[N,K]^T
// CTA tile 128x128, 2 CTA/SM, 3-stage pipeline, A-fragment double-buffer.
// Persistent CTAs + work-stealing.  qkv_mode: fused RoPE + hi/lo epilogue.
// ---------------------------------------------------------------------------
#define TILE_B   8192               // 128 rows * 64B (packed, swizzled)
#define STAGE_B  (4 * TILE_B)       // 32768
#define GEMM_STAGES 3
#define GEMM_SMEM_BYTES (GEMM_STAGES * STAGE_B)   // 98304
#define CT_PITCH 132

__global__ __launch_bounds__(256, 2) void gemm_mma_kernel(
    const __nv_bfloat16* __restrict__ Ahi, const __nv_bfloat16* __restrict__ Alo,
    const __nv_bfloat16* __restrict__ Bhi, const __nv_bfloat16* __restrict__ Blo,
    float* __restrict__ C, int N, int K, int Mtiles, int total_tiles,
    unsigned* __restrict__ counter, int qkv_mode,
    const float* __restrict__ ct, const float* __restrict__ st,
    __nv_bfloat16* __restrict__ qhi, __nv_bfloat16* __restrict__ qlo,
    __nv_bfloat16* __restrict__ khi, __nv_bfloat16* __restrict__ klo,
    __nv_bfloat16* __restrict__ vhi, __nv_bfloat16* __restrict__ vlo)
{
    extern __shared__ __align__(128) char smem[];
    __shared__ unsigned s_tile;
    const uint32_t sbase = smem_u32(smem);
    const int tid = threadIdx.x;
    const int wid = tid >> 5;
    const int lane = tid & 31;
    const int NC = K / 32;

    const int warp_m = wid & 1;
    const int warp_n = wid >> 1;
    const int q = lane >> 3;
    const int r = lane & 7;
    const int gp = lane >> 2;
    const int tg = lane & 3;

    for (;;) {
        if (tid == 0) s_tile = atomicAdd(counter, 1u);
        __syncthreads();                 // tile uniform + prev epilogue done
        const unsigned t = s_tile;
        if (t >= (unsigned)total_tiles) return;
        const int m0 = ((int)t % Mtiles) * 128;
        const int n0 = ((int)t / Mtiles) * 128;

        const __nv_bfloat16* srcs[4] = {Ahi, Alo, Bhi, Blo};
        const int row0s[4] = {m0, m0, n0, n0};

        float acc[4][4][4];
#pragma unroll
        for (int mt = 0; mt < 4; mt++)
#pragma unroll
            for (int nt = 0; nt < 4; nt++)
#pragma unroll
                for (int e = 0; e < 4; e++) acc[mt][nt][e] = 0.0f;

        auto load_stage = [&](int stage, int c) {
            const uint32_t st_ = sbase + (uint32_t)stage * STAGE_B;
#pragma unroll
            for (int i = 0; i < 8; i++) {
                int g = tid + i * 256;
                int sel = g >> 9;
                int rem = g & 511;
                int row = rem >> 2;
                int u = rem & 3;
                const char* gsrc = (const char*)(srcs[sel] + (size_t)(row0s[sel] + row) * K)
                                   + c * 64 + u * 16;
                uint32_t dst = st_ + (uint32_t)sel * TILE_B + tile_off(row, u);
                CP_ASYNC16(dst, gsrc);
            }
            CP_COMMIT();
        };

        load_stage(0, 0);
        load_stage(1, 1);

        int stage = 0;
        for (int c = 0; c < NC; c++) {
            if (c + 1 < NC) { CP_WAIT(1); }
            else           { CP_WAIT(0); }
            __syncthreads();
            if (c + 2 < NC) load_stage((stage + 2) % GEMM_STAGES, c + 2);

            const uint32_t st_ = sbase + (uint32_t)stage * STAGE_B;
            const uint32_t aBase = st_;
            const uint32_t bBase = st_ + 2 * TILE_B;

#pragma unroll
            for (int kstep = 0; kstep < 2; kstep++) {
                uint32_t bh0[4], bh1[4], bl0[4], bl1[4];
                const int bunit = kstep * 2 + (q & 1);
                {
                    int brow0 = warp_n * 32 + (q >> 1) * 8 + r;
                    uint32_t a0 = bBase + tile_off(brow0, bunit);
                    LDSM_X4(bh0[0], bh0[1], bh0[2], bh0[3], a0);
                    LDSM_X4(bl0[0], bl0[1], bl0[2], bl0[3], a0 + TILE_B);
                    uint32_t a1 = bBase + tile_off(brow0 + 16, bunit);
                    LDSM_X4(bh1[0], bh1[1], bh1[2], bh1[3], a1);
                    LDSM_X4(bl1[0], bl1[1], bl1[2], bl1[3], a1 + TILE_B);
                }
                const int aunit = kstep * 2 + (q >> 1);
                const int abase_row = warp_m * 64 + (q & 1) * 8 + r;

                uint32_t ahA[4], alA[4], ahB[4], alB[4];
                {
                    uint32_t addr = aBase + tile_off(abase_row, aunit);
                    LDSM_X4(ahA[0], ahA[1], ahA[2], ahA[3], addr);
                    LDSM_X4(alA[0], alA[1], alA[2], alA[3], addr + TILE_B);
                }
#pragma unroll
                for (int mt = 0; mt < 4; mt++) {
                    uint32_t* ah = (mt & 1) ? ahB : ahA;
                    uint32_t* al = (mt & 1) ? alB : alA;
                    if (mt < 3) {
                        uint32_t* nh = (mt & 1) ? ahA : ahB;
                        uint32_t* nl = (mt & 1) ? alA : alB;
                        uint32_t addr = aBase + tile_off(abase_row + (mt + 1) * 16, aunit);
                        LDSM_X4(nh[0], nh[1], nh[2], nh[3], addr);
                        LDSM_X4(nl[0], nl[1], nl[2], nl[3], addr + TILE_B);
                    }
                    MMA_BF16(acc[mt][0], ah, bh0[0], bh0[1]);
                    MMA_BF16(acc[mt][1], ah, bh0[2], bh0[3]);
                    MMA_BF16(acc[mt][2], ah, bh1[0], bh1[1]);
                    MMA_BF16(acc[mt][3], ah, bh1[2], bh1[3]);

                    MMA_BF16(acc[mt][0], ah, bl0[0], bl0[1]);
                    MMA_BF16(acc[mt][1], ah, bl0[2], bl0[3]);
                    MMA_BF16(acc[mt][2], ah, bl1[0], bl1[1]);
                    MMA_BF16(acc[mt][3], ah, bl1[2], bl1[3]);

                    MMA_BF16(acc[mt][0], al, bh0[0], bh0[1]);
                    MMA_BF16(acc[mt][1], al, bh0[2], bh0[3]);
                    MMA_BF16(acc[mt][2], al, bh1[0], bh1[1]);
                    MMA_BF16(acc[mt][3], al, bh1[2], bh1[3]);
                }
            }
            stage = (stage + 1) % GEMM_STAGES;
        }

        // ------------------------ Epilogue ------------------------
        if (!qkv_mode) {
#pragma unroll
            for (int mt = 0; mt < 4; mt++) {
#pragma unroll
                for (int nt = 0; nt < 4; nt++) {
                    int row = m0 + warp_m * 64 + mt * 16 + gp;
                    int col = n0 + warp_n * 32 + nt * 8 + tg * 2;
                    *(float2*)&C[(size_t)row * N + col] =
                        make_float2(acc[mt][nt][0], acc[mt][nt][1]);
                    *(float2*)&C[(size_t)(row + 8) * N + col] =
                        make_float2(acc[mt][nt][2], acc[mt][nt][3]);
                }
            }
        } else if (n0 >= K_END) {
            // V tile: straight hi/lo split from registers
            int colbase = n0 - K_END;
#pragma unroll
            for (int mt = 0; mt < 4; mt++) {
#pragma unroll
                for (int nt = 0; nt < 4; nt++) {
                    int r0 = m0 + warp_m * 64 + mt * 16 + gp;
                    int cc = colbase + warp_n * 32 + nt * 8 + tg * 2;
#pragma unroll
                    for (int hf = 0; hf < 2; hf++) {
                        float o0 = acc[mt][nt][2 * hf];
                        float o1 = acc[mt][nt][2 * hf + 1];
                        float h0 = __bfloat162float(__float2bfloat16_rn(o0));
                        float h1 = __bfloat162float(__float2bfloat16_rn(o1));
                        size_t off = (size_t)(r0 + hf * 8) * KVW_ + cc;
                        *(uint32_t*)(vhi + off) = pack_bf16(h0, h1);
                        *(uint32_t*)(vlo + off) = pack_bf16(o0 - h0, o1 - h1);
                    }
                }
            }
        } else {
            // Q or K tile: stage fp32 tile to smem, rope-pair, split, store
            __syncthreads();
            float* ctile = (float*)smem;
#pragma unroll
            for (int mt = 0; mt < 4; mt++) {
#pragma unroll
                for (int nt = 0; nt < 4; nt++) {
                    int r0 = warp_m * 64 + mt * 16 + gp;
                    int cc = warp_n * 32 + nt * 8 + tg * 2;
                    ctile[r0 * CT_PITCH + cc] = acc[mt][nt][0];
                    ctile[r0 * CT_PITCH + cc + 1] = acc[mt][nt][1];
                    ctile[(r0 + 8) * CT_PITCH + cc] = acc[mt][nt][2];
                    ctile[(r0 + 8) * CT_PITCH + cc + 1] = acc[mt][nt][3];
                }
            }
            __syncthreads();

            __nv_bfloat16 *dhi, *dlo;
            int width, colbase;
            if (n0 < Q_END) { dhi = qhi; dlo = qlo; width = H_;   colbase = n0; }
            else            { dhi = khi; dlo = klo; width = KVW_; colbase = n0 - Q_END; }

#pragma unroll
            for (int it = 0; it < 16; it++) {
                int g = tid + it * 256;     // 0..4095: 128 rows x 32 pairs
                int row = g >> 5;
                int d2 = (g & 31) * 2;
                float2 x1 = *(float2*)&ctile[row * CT_PITCH + d2];
                float2 x2 = *(float2*)&ctile[row * CT_PITCH + 64 + d2];
                int s = m0 + row;
                float2 cv = *(const float2*)&ct[s * 64 + d2];
                float2 sv = *(const float2*)&st[s * 64 + d2];
                float y1a = x1.x * cv.x - x2.x * sv.x;
                float y1b = x1.y * cv.y - x2.y * sv.y;
                float y2a = x1.x * sv.x + x2.x * cv.x;
                float y2b = x1.y * sv.y + x2.y * cv.y;

                float h1a = __bfloat162float(__float2bfloat16_rn(y1a));
                float h1b = __bfloat162float(__float2bfloat16_rn(y1b));
                float h2a = __bfloat162float(__float2bfloat16_rn(y2a));
                float h2b = __bfloat162float(__float2bfloat16_rn(y2b));

                size_t ob = (size_t)s * width + colbase + d2;
                *(uint32_t*)(dhi + ob)      = pack_bf16(h1a, h1b);
                *(uint32_t*)(dlo + ob)      = pack_bf16(y1a - h1a, y1b - h1b);
                *(uint32_t*)(dhi + ob + 64) = pack_bf16(h2a, h2b);
                *(uint32_t*)(dlo + ob + 64) = pack_bf16(y2a - h2a, y2b - h2b);
            }
        }
    }
}

// ---------------------------------------------------------------------------
// Flash attention via mma.sync, bf16x3 QK^T and bf16x3 PV, causal, GQA.
// BQ=64 (4 warps), 2 CTA/SM, persistent + work-stealing, heavy-qb-first.
// ---------------------------------------------------------------------------
#define AP_ 136
#define APB_ 272
#define Q_COMP_B 17408
#define KV_COMP_B 8704
#define KV_STAGE_B (4 * KV_COMP_B)
#define ATTN_SMEM_BYTES (2 * Q_COMP_B + 2 * KV_STAGE_B)   // 104448

__global__ __launch_bounds__(128, 2) void flash_attn_mma_kernel(
    const __nv_bfloat16* __restrict__ qhi, const __nv_bfloat16* __restrict__ qlo,
    const __nv_bfloat16* __restrict__ khi, const __nv_bfloat16* __restrict__ klo,
    const __nv_bfloat16* __restrict__ vhi, const __nv_bfloat16* __restrict__ vlo,
    __nv_bfloat16* __restrict__ out_hi, __nv_bfloat16* __restrict__ out_lo,
    int total_tiles, unsigned* __restrict__ counter)
{
    extern __shared__ __align__(128) char smA[];
    __shared__ unsigned s_tile;
    const uint32_t sb = smem_u32(smA);
    const int tid = threadIdx.x;
    const int wid = tid >> 5;
    const int lane = tid & 31;
    const int gp = lane >> 2;
    const int tg = lane & 3;

    const uint32_t Qhi_s = sb;
    const uint32_t Qlo_s = sb + Q_COMP_B;
    const uint32_t Stage_s = sb + 2 * Q_COMP_B;
    const float scale = 0.08838834764831845f;

    for (;;) {
        if (tid == 0) s_tile = atomicAdd(counter, 1u);
        __syncthreads();
        const unsigned t = s_tile;
        if (t >= (unsigned)total_tiles) return;
        const int qb = (S_ / 64 - 1) - (int)(t >> 5);  // heavy first
        const int head = (int)(t & 31);
        const int kvh = head >> 2;
        const int q0 = qb * 64;

#pragma unroll
        for (int i = 0; i < 16; i++) {
            int g = tid + i * 128;
            int comp = g >> 10;
            int rem = g & 1023;
            int row = rem >> 4;
            int u = rem & 15;
            const __nv_bfloat16* src = (comp ? qlo : qhi)
                + (size_t)(q0 + row) * H_ + head * HD_ + u * 8;
            uint32_t dst = (comp ? Qlo_s : Qhi_s) + (uint32_t)(row * APB_ + u * 16);
            CP_ASYNC16(dst, src);
        }
        CP_COMMIT();

        const int kb_max = 2 * qb + 1;

        auto load_kv = [&](int stage, int kb) {
            uint32_t st = Stage_s + (uint32_t)stage * KV_STAGE_B;
            const __nv_bfloat16* bases[4] = {khi, klo, vhi, vlo};
#pragma unroll
            for (int i = 0; i < 16; i++) {
                int g = tid + i * 128;
                int comp = g >> 9;
                int rem = g & 511;
                int row = rem >> 4;
                int u = rem & 15;
                const __nv_bfloat16* src = bases[comp]
                    + (size_t)(kb * 32 + row) * KVW_ + kvh * HD_ + u * 8;
                CP_ASYNC16(st + (uint32_t)(comp * KV_COMP_B + row * APB_ + u * 16), src);
            }
            CP_COMMIT();
        };

        load_kv(0, 0);

        float O[16][4];
        float m_i[2] = {-1e30f, -1e30f};
        float l_i[2] = {0.0f, 0.0f};
#pragma unroll
        for (int nt = 0; nt < 16; nt++)
#pragma unroll
            for (int e = 0; e < 4; e++) O[nt][e] = 0.0f;

        for (int kb = 0; kb <= kb_max; kb++) {
            if (kb < kb_max) { load_kv((kb + 1) & 1, kb + 1); CP_WAIT(1); }
            else             { CP_WAIT(0); }
            __syncthreads();

            const uint32_t st = Stage_s + (uint32_t)(kb & 1) * KV_STAGE_B;
            const uint32_t Ks_hi = st;
            const uint32_t Ks_lo = st + KV_COMP_B;
            const uint32_t Vs_hi = st + 2 * KV_COMP_B;
            const uint32_t Vs_lo = st + 3 * KV_COMP_B;

            float S[4][4];
#pragma unroll
            for (int tt = 0; tt < 4; tt++)
#pragma unroll
                for (int e = 0; e < 4; e++) S[tt][e] = 0.0f;

#pragma unroll
            for (int kt = 0; kt < 8; kt++) {
                uint32_t aoff = (uint32_t)((wid * 16 + (lane & 15)) * APB_
                                           + (kt * 16 + (lane >> 4) * 8) * 2);
                uint32_t ahi[4], alo[4];
                LDSM_X4(ahi[0], ahi[1], ahi[2], ahi[3], Qhi_s + aoff);
                LDSM_X4(alo[0], alo[1], alo[2], alo[3], Qlo_s + aoff);

                uint32_t bh[2][4], bl[2][4];
#pragma unroll
                for (int pr = 0; pr < 2; pr++) {
                    uint32_t boff = (uint32_t)((pr * 16 + (lane >> 4) * 8 + (lane & 7)) * APB_
                                               + (kt * 16 + ((lane >> 3) & 1) * 8) * 2);
                    LDSM_X4(bh[pr][0], bh[pr][1], bh[pr][2], bh[pr][3], Ks_hi + boff);
                    LDSM_X4(bl[pr][0], bl[pr][1], bl[pr][2], bl[pr][3], Ks_lo + boff);
                }
                MMA_BF16(S[0], ahi, bh[0][0], bh[0][1]);
                MMA_BF16(S[1], ahi, bh[0][2], bh[0][3]);
                MMA_BF16(S[2], ahi, bh[1][0], bh[1][1]);
                MMA_BF16(S[3], ahi, bh[1][2], bh[1][3]);

                MMA_BF16(S[0], ahi, bl[0][0], bl[0][1]);
                MMA_BF16(S[1], ahi, bl[0][2], bl[0][3]);
                MMA_BF16(S[2], ahi, bl[1][0], bl[1][1]);
                MMA_BF16(S[3], ahi, bl[1][2], bl[1][3]);

                MMA_BF16(S[0], alo, bh[0][0], bh[0][1]);
                MMA_BF16(S[1], alo, bh[0][2], bh[0][3]);
                MMA_BF16(S[2], alo, bh[1][0], bh[1][1]);
                MMA_BF16(S[3], alo, bh[1][2], bh[1][3]);
            }

            if (kb >= 2 * qb) {
#pragma unroll
                for (int tt = 0; tt < 4; tt++) {
                    int colb = kb * 32 + tt * 8 + 2 * tg;
#pragma unroll
                    for (int e = 0; e < 4; e++) {
                        int col = colb + (e & 1);
                        int row = q0 + wid * 16 + gp + ((e >= 2) ? 8 : 0);
                        S[tt][e] = (col <= row) ? S[tt][e] * scale : -1e30f;
                    }
                }
            } else {
#pragma unroll
                for (int tt = 0; tt < 4; tt++)
#pragma unroll
                    for (int e = 0; e < 4; e++) S[tt][e] *= scale;
            }

#pragma unroll
            for (int h = 0; h < 2; h++) {
                float mx = -1e30f;
#pragma unroll
                for (int tt = 0; tt < 4; tt++)
                    mx = fmaxf(mx, fmaxf(S[tt][2 * h], S[tt][2 * h + 1]));
                mx = fmaxf(mx, __shfl_xor_sync(0xffffffffu, mx, 1));
                mx = fmaxf(mx, __shfl_xor_sync(0xffffffffu, mx, 2));
                float m_new = fmaxf(m_i[h], mx);
                float alpha = __expf(m_i[h] - m_new);
                float sum = 0.0f;
#pragma unroll
                for (int tt = 0; tt < 4; tt++) {
                    S[tt][2 * h]     = __expf(S[tt][2 * h] - m_new);
                    S[tt][2 * h + 1] = __expf(S[tt][2 * h + 1] - m_new);
                    sum += S[tt][2 * h] + S[tt][2 * h + 1];
                }
                sum += __shfl_xor_sync(0xffffffffu, sum, 1);
                sum += __shfl_xor_sync(0xffffffffu, sum, 2);
                l_i[h] = l_i[h] * alpha + sum;
                m_i[h] = m_new;
#pragma unroll
                for (int nt = 0; nt < 16; nt++) {
                    O[nt][2 * h] *= alpha;
                    O[nt][2 * h + 1] *= alpha;
                }
            }

#pragma unroll
            for (int kt2 = 0; kt2 < 2; kt2++) {
                uint32_t phi[4], plo[4];
                {
                    float* p0 = S[2 * kt2];
                    float* p1 = S[2 * kt2 + 1];
                    float h00 = __bfloat162float(__float2bfloat16_rn(p0[0]));
                    float h01 = __bfloat162float(__float2bfloat16_rn(p0[1]));
                    float h02 = __bfloat162float(__float2bfloat16_rn(p0[2]));
                    float h03 = __bfloat162float(__float2bfloat16_rn(p0[3]));
                    float h10 = __bfloat162float(__float2bfloat16_rn(p1[0]));
                    float h11 = __bfloat162float(__float2bfloat16_rn(p1[1]));
                    float h12 = __bfloat162float(__float2bfloat16_rn(p1[2]));
                    float h13 = __bfloat162float(__float2bfloat16_rn(p1[3]));
                    phi[0] = pack_bf16(h00, h01);
                    phi[1] = pack_bf16(h02, h03);
                    phi[2] = pack_bf16(h10, h11);
                    phi[3] = pack_bf16(h12, h13);
                    plo[0] = pack_bf16(p0[0] - h00, p0[1] - h01);
                    plo[1] = pack_bf16(p0[2] - h02, p0[3] - h03);
                    plo[2] = pack_bf16(p1[0] - h10, p1[1] - h11);
                    plo[3] = pack_bf16(p1[2] - h12, p1[3] - h13);
                }
#pragma unroll
                for (int dq = 0; dq < 4; dq++) {
                    uint32_t bh0[4], bl0[4], bh1[4], bl1[4];
#pragma unroll
                    for (int half = 0; half < 2; half++) {
                        int dp = 2 * dq + half;
                        uint32_t voff = (uint32_t)((kt2 * 16 + ((lane >> 3) & 1) * 8 + (lane & 7)) * APB_
                                                   + (dp * 16 + (lane >> 4) * 8) * 2);
                        if (half == 0) {
                            LDSM_X4_T(bh0[0], bh0[1], bh0[2], bh0[3], Vs_hi + voff);
                            LDSM_X4_T(bl0[0], bl0[1], bl0[2], bl0[3], Vs_lo + voff);
                        } else {
                            LDSM_X4_T(bh1[0], bh1[1], bh1[2], bh1[3], Vs_hi + voff);
                            LDSM_X4_T(bl1[0], bl1[1], bl1[2], bl1[3], Vs_lo + voff);
                        }
                    }
                    float* O0 = O[4 * dq + 0];
                    float* O1 = O[4 * dq + 1];
                    float* O2 = O[4 * dq + 2];
                    float* O3 = O[4 * dq + 3];
                    MMA_BF16(O0, phi, bh0[0], bh0[1]);
                    MMA_BF16(O1, phi, bh0[2], bh0[3]);
                    MMA_BF16(O2, phi, bh1[0], bh1[1]);
                    MMA_BF16(O3, phi, bh1[2], bh1[3]);

                    MMA_BF16(O0, phi, bl0[0], bl0[1]);
                    MMA_BF16(O1, phi, bl0[2], bl0[3]);
                    MMA_BF16(O2, phi, bl1[0], bl1[1]);
                    MMA_BF16(O3, phi, bl1[2], bl1[3]);

                    MMA_BF16(O0, plo, bh0[0], bh0[1]);
                    MMA_BF16(O1, plo, bh0[2], bh0[3]);
                    MMA_BF16(O2, plo, bh1[0], bh1[1]);
                    MMA_BF16(O3, plo, bh1[2], bh1[3]);
                }
            }
            __syncthreads();
        }

#pragma unroll
        for (int h = 0; h < 2; h++) {
            float inv = 1.0f / l_i[h];
            int row = q0 + wid * 16 + gp + h * 8;
            size_t base = (size_t)row * H_ + head * HD_;
#pragma unroll
            for (int nt = 0; nt < 16; nt++) {
                float o0 = O[nt][2 * h] * inv;
                float o1 = O[nt][2 * h + 1] * inv;
                float hh0 = __bfloat162float(__float2bfloat16_rn(o0));
                float hh1 = __bfloat162float(__float2bfloat16_rn(o1));
                size_t off = base + nt * 8 + 2 * tg;
                *(uint32_t*)(out_hi + off) = pack_bf16(hh0, hh1);
                *(uint32_t*)(out_lo + off) = pack_bf16(o0 - hh0, o1 - hh1);
            }
        }
    }
}

// ---------------------------------------------------------------------------
extern "C" void kernel_launch(void* const* d_in, const int* in_sizes, int n_in,
                              void* d_out, int out_size)
{
    const float* hidden = (const float*)d_in[0];   // [1,2048,4096]
    const float* Wqkv   = (const float*)d_in[1];   // [6144,4096]
    const float* Wo     = (const float*)d_in[2];   // [4096,4096]
    float* out = (float*)d_out;                    // [1,2048,4096]

    __nv_bfloat16 *hid_hi, *hid_lo, *wqkv_hi, *wqkv_lo, *wo_hi, *wo_lo, *attn_hi, *attn_lo;
    __nv_bfloat16 *q_hi, *q_lo, *k_hi, *k_lo, *v_hi, *v_lo;
    float *ct, *st;
    unsigned* counters;
    cudaGetSymbolAddress((void**)&hid_hi, g_hid_hi);
    cudaGetSymbolAddress((void**)&hid_lo, g_hid_lo);
    cudaGetSymbolAddress((void**)&wqkv_hi, g_wqkv_hi);
    cudaGetSymbolAddress((void**)&wqkv_lo, g_wqkv_lo);
    cudaGetSymbolAddress((void**)&wo_hi, g_wo_hi);
    cudaGetSymbolAddress((void**)&wo_lo, g_wo_lo);
    cudaGetSymbolAddress((void**)&attn_hi, g_attn_hi);
    cudaGetSymbolAddress((void**)&attn_lo, g_attn_lo);
    cudaGetSymbolAddress((void**)&q_hi, g_q_hi);
    cudaGetSymbolAddress((void**)&q_lo, g_q_lo);
    cudaGetSymbolAddress((void**)&k_hi, g_k_hi);
    cudaGetSymbolAddress((void**)&k_lo, g_k_lo);
    cudaGetSymbolAddress((void**)&v_hi, g_v_hi);
    cudaGetSymbolAddress((void**)&v_lo, g_v_lo);
    cudaGetSymbolAddress((void**)&ct, g_cos);
    cudaGetSymbolAddress((void**)&st, g_sin);
    cudaGetSymbolAddress((void**)&counters, g_counters);

    int smCount = 148;
    cudaDeviceGetAttribute(&smCount, cudaDevAttrMultiProcessorCount, 0);
    const int gemm_grid = 2 * smCount;
    const int attn_grid = 2 * smCount;

    cudaFuncSetAttribute(gemm_mma_kernel,
                         cudaFuncAttributeMaxDynamicSharedMemorySize, GEMM_SMEM_BYTES);
    cudaFuncSetAttribute(flash_attn_mma_kernel,
                         cudaFuncAttributeMaxDynamicSharedMemorySize, ATTN_SMEM_BYTES);

    // reset counters; rope tables
    cudaMemsetAsync(counters, 0, 4 * sizeof(unsigned));
    rope_table_kernel<<<S_, 64>>>(ct, st);

    // 0) fused split-convert of all inputs (single launch)
    {
        cvt_all_kernel<<<(N4_ALL + 255) / 256, 256>>>(
            hidden, Wqkv, Wo,
            hid_hi, hid_lo, wqkv_hi, wqkv_lo, wo_hi, wo_lo);
    }

    // 1) QKV projection, fused RoPE + split epilogue
    {
        int mt = S_ / 128, nt = QKV_O / 128;
        gemm_mma_kernel<<<gemm_grid, 256, GEMM_SMEM_BYTES>>>(
            hid_hi, hid_lo, wqkv_hi, wqkv_lo, nullptr, QKV_O, H_, mt, mt * nt,
            counters + 0, 1, ct, st,
            q_hi, q_lo, k_hi, k_lo, v_hi, v_lo);
    }

    // 2) Flash attention (BQ=64, 2 CTA/SM, persistent + work-stealing)
    {
        int tiles = (S_ / 64) * NH_;   // 1024
        flash_attn_mma_kernel<<<attn_grid, 128, ATTN_SMEM_BYTES>>>(
            q_hi, q_lo, k_hi, k_lo, v_hi, v_lo, attn_hi, attn_lo,
            tiles, counters + 1);
    }

    // 3) Output projection (plain fp32 epilogue)
    {
        int mt = S_ / 128, nt = H_ / 128;
        gemm_mma_kernel<<<gemm_grid, 256, GEMM_SMEM_BYTES>>>(
            attn_hi, attn_lo, wo_hi, wo_lo, out, H_, H_, mt, mt * nt,
            counters + 2, 0, ct, st,
            nullptr, nullptr, nullptr, nullptr, nullptr, nullptr);
    }
}

// round 16
// speedup vs baseline: 1.0964x; 1.0004x over previous
#include <cuda_runtime.h>
#include <cuda_bf16.h>
#include <math.h>
#include <stdint.h>

// Problem constants
#define B_      1
#define S_      2048
#define H_      4096
#define NH_     32
#define NKV_    8
#define HD_     128
#define QKV_O   ((NH_ + 2 * NKV_) * HD_)   // 6144
#define Q_END   (NH_ * HD_)                // 4096
#define K_END   (Q_END + NKV_ * HD_)       // 5120
#define KVW_    (NKV_ * HD_)               // 1024

// ---------------------------------------------------------------------------
// Scratch (no allocations allowed)
// ---------------------------------------------------------------------------
__device__ __nv_bfloat16 g_hid_hi[S_ * H_];
__device__ __nv_bfloat16 g_hid_lo[S_ * H_];
__device__ __nv_bfloat16 g_wqkv_hi[QKV_O * H_];
__device__ __nv_bfloat16 g_wqkv_lo[QKV_O * H_];
__device__ __nv_bfloat16 g_wo_hi[H_ * H_];
__device__ __nv_bfloat16 g_wo_lo[H_ * H_];
__device__ __nv_bfloat16 g_attn_hi[S_ * H_];
__device__ __nv_bfloat16 g_attn_lo[S_ * H_];

__device__ __nv_bfloat16 g_q_hi[S_ * H_];            // RoPE'd Q  [2048, 4096]
__device__ __nv_bfloat16 g_q_lo[S_ * H_];
__device__ __nv_bfloat16 g_k_hi[S_ * KVW_];          // RoPE'd K  [2048, 1024]
__device__ __nv_bfloat16 g_k_lo[S_ * KVW_];
__device__ __nv_bfloat16 g_v_hi[S_ * KVW_];          // V         [2048, 1024]
__device__ __nv_bfloat16 g_v_lo[S_ * KVW_];

__device__ float g_cos[S_ * 64];
__device__ float g_sin[S_ * 64];
__device__ unsigned g_counters[4];      // work-stealing tile counters

// ---------------------------------------------------------------------------
// Baseline-ISA PTX helpers
// ---------------------------------------------------------------------------
__device__ __forceinline__ uint32_t smem_u32(const void* p) {
    uint32_t a;
    asm("{ .reg .u64 t; cvta.to.shared.u64 t, %1; cvt.u32.u64 %0, t; }"
        : "=r"(a) : "l"(p));
    return a;
}

#define CP_ASYNC16(dst, src) \
    asm volatile("cp.async.cg.shared.global [%0], [%1], 16;" \
        :: "r"(dst), "l"(src) : "memory")
#define CP_COMMIT() asm volatile("cp.async.commit_group;" ::: "memory")
#define CP_WAIT(n)  asm volatile("cp.async.wait_group %0;" :: "n"(n) : "memory")

#define LDSM_X4(r0, r1, r2, r3, addr) \
    asm volatile("ldmatrix.sync.aligned.m8n8.x4.shared.b16 {%0,%1,%2,%3}, [%4];" \
        : "=r"(r0), "=r"(r1), "=r"(r2), "=r"(r3) : "r"(addr))

#define LDSM_X4_T(r0, r1, r2, r3, addr) \
    asm volatile("ldmatrix.sync.aligned.m8n8.x4.trans.shared.b16 {%0,%1,%2,%3}, [%4];" \
        : "=r"(r0), "=r"(r1), "=r"(r2), "=r"(r3) : "r"(addr))

#define MMA_BF16(d, a, b0, b1) \
    asm volatile("mma.sync.aligned.m16n8k16.row.col.f32.bf16.bf16.f32 " \
        "{%0,%1,%2,%3}, {%4,%5,%6,%7}, {%8,%9}, {%0,%1,%2,%3};" \
        : "+f"((d)[0]), "+f"((d)[1]), "+f"((d)[2]), "+f"((d)[3]) \
        : "r"((a)[0]), "r"((a)[1]), "r"((a)[2]), "r"((a)[3]), "r"(b0), "r"(b1))

__device__ __forceinline__ uint32_t pack_bf16(float x, float y) {
    __nv_bfloat162 h = __floats2bfloat162_rn(x, y);
    return *(uint32_t*)&h;
}

// Packed tile swizzle (conflict-free for cp.async stores + ldmatrix phases)
__device__ __forceinline__ uint32_t tile_off(int row, int unit) {
    uint32_t off = (uint32_t)((row >> 1) * 128 + (row & 1) * 64 + unit * 16);
    return off ^ ((off >> 3) & 0x70);
}

// ---------------------------------------------------------------------------
// RoPE tables (double-precision sincos, computed once)
// ---------------------------------------------------------------------------
__global__ void rope_table_kernel(float* __restrict__ ct, float* __restrict__ st)
{
    int s = blockIdx.x;
    int d2 = threadIdx.x;     // 0..63
    double inv = exp(-((double)(2 * d2) / (double)HD_) * 9.210340371976184);
    double ang = (double)s * inv;
    double sv, cv;
    sincos(ang, &sv, &cv);
    ct[s * 64 + d2] = (float)cv;
    st[s * 64 + d2] = (float)sv;
}

// ---------------------------------------------------------------------------
// Fused fp32 -> (bf16 hi, bf16 lo) split for all three inputs, one launch.
// ---------------------------------------------------------------------------
#define N4_HID  (S_ * H_ / 4)              // 2097152
#define N4_WQKV (QKV_O * H_ / 4)           // 6291456
#define N4_WO   (H_ * H_ / 4)              // 4194304
#define N4_ALL  (N4_HID + N4_WQKV + N4_WO) // 12582912

__global__ void cvt_all_kernel(
    const float* __restrict__ hid, const float* __restrict__ wqkv,
    const float* __restrict__ wo,
    __nv_bfloat16* __restrict__ hid_hi, __nv_bfloat16* __restrict__ hid_lo,
    __nv_bfloat16* __restrict__ wqkv_hi, __nv_bfloat16* __restrict__ wqkv_lo,
    __nv_bfloat16* __restrict__ wo_hi, __nv_bfloat16* __restrict__ wo_lo)
{
    int i = blockIdx.x * blockDim.x + threadIdx.x;
    if (i >= N4_ALL) return;
    const float* src;
    __nv_bfloat16 *hi, *lo;
    int j;
    if (i < N4_HID)                { src = hid;  hi = hid_hi;  lo = hid_lo;  j = i; }
    else if (i < N4_HID + N4_WQKV) { src = wqkv; hi = wqkv_hi; lo = wqkv_lo; j = i - N4_HID; }
    else                           { src = wo;   hi = wo_hi;   lo = wo_lo;   j = i - N4_HID - N4_WQKV; }

    float4 v = ((const float4*)src)[j];
    __nv_bfloat16 h0 = __float2bfloat16_rn(v.x);
    __nv_bfloat16 h1 = __float2bfloat16_rn(v.y);
    __nv_bfloat16 h2 = __float2bfloat16_rn(v.z);
    __nv_bfloat16 h3 = __float2bfloat16_rn(v.w);
    __nv_bfloat16 l0 = __float2bfloat16_rn(v.x - __bfloat162float(h0));
    __nv_bfloat16 l1 = __float2bfloat16_rn(v.y - __bfloat162float(h1));
    __nv_bfloat16 l2 = __float2bfloat16_rn(v.z - __bfloat162float(h2));
    __nv_bfloat16 l3 = __float2bfloat16_rn(v.w - __bfloat162float(h3));
    ((__nv_bfloat162*)hi)[j * 2 + 0] = __nv_bfloat162(h0, h1);
    ((__nv_bfloat162*)hi)[j * 2 + 1] = __nv_bfloat162(h2, h3);
    ((__nv_bfloat162*)lo)[j * 2 + 0] = __nv_bfloat162(l0, l1);
    ((__nv_bfloat162*)lo)[j * 2 + 1] = __nv_bfloat162(l2, l3);
}

// ---------------------------------------------------------------------------
// bf16x3 GEMM via mma.sync (HMMA):  C[M,N] = A[M,K] * B[N,K]^T
// CTA tile 128x128, 2 CTA/SM, 3-stage pipeline, A-fragment double-buffer.
// Persistent CTAs + work-stealing.  qkv_mode: fused RoPE + hi/lo epilogue.
// (unchanged from round-15 champion)
// ---------------------------------------------------------------------------
#define TILE_B   8192               // 128 rows * 64B (packed, swizzled)
#define STAGE_B  (4 * TILE_B)       // 32768
#define GEMM_STAGES 3
#define GEMM_SMEM_BYTES (GEMM_STAGES * STAGE_B)   // 98304
#define CT_PITCH 132

__global__ __launch_bounds__(256, 2) void gemm_mma_kernel(
    const __nv_bfloat16* __restrict__ Ahi, const __nv_bfloat16* __restrict__ Alo,
    const __nv_bfloat16* __restrict__ Bhi, const __nv_bfloat16* __restrict__ Blo,
    float* __restrict__ C, int N, int K, int Mtiles, int total_tiles,
    unsigned* __restrict__ counter, int qkv_mode,
    const float* __restrict__ ct, const float* __restrict__ st,
    __nv_bfloat16* __restrict__ qhi, __nv_bfloat16* __restrict__ qlo,
    __nv_bfloat16* __restrict__ khi, __nv_bfloat16* __restrict__ klo,
    __nv_bfloat16* __restrict__ vhi, __nv_bfloat16* __restrict__ vlo)
{
    extern __shared__ __align__(128) char smem[];
    __shared__ unsigned s_tile;
    const uint32_t sbase = smem_u32(smem);
    const int tid = threadIdx.x;
    const int wid = tid >> 5;
    const int lane = tid & 31;
    const int NC = K / 32;

    const int warp_m = wid & 1;
    const int warp_n = wid >> 1;
    const int q = lane >> 3;
    const int r = lane & 7;
    const int gp = lane >> 2;
    const int tg = lane & 3;

    for (;;) {
        if (tid == 0) s_tile = atomicAdd(counter, 1u);
        __syncthreads();                 // tile uniform + prev epilogue done
        const unsigned t = s_tile;
        if (t >= (unsigned)total_tiles) return;
        const int m0 = ((int)t % Mtiles) * 128;
        const int n0 = ((int)t / Mtiles) * 128;

        const __nv_bfloat16* srcs[4] = {Ahi, Alo, Bhi, Blo};
        const int row0s[4] = {m0, m0, n0, n0};

        float acc[4][4][4];
#pragma unroll
        for (int mt = 0; mt < 4; mt++)
#pragma unroll
            for (int nt = 0; nt < 4; nt++)
#pragma unroll
                for (int e = 0; e < 4; e++) acc[mt][nt][e] = 0.0f;

        auto load_stage = [&](int stage, int c) {
            const uint32_t st_ = sbase + (uint32_t)stage * STAGE_B;
#pragma unroll
            for (int i = 0; i < 8; i++) {
                int g = tid + i * 256;
                int sel = g >> 9;
                int rem = g & 511;
                int row = rem >> 2;
                int u = rem & 3;
                const char* gsrc = (const char*)(srcs[sel] + (size_t)(row0s[sel] + row) * K)
                                   + c * 64 + u * 16;
                uint32_t dst = st_ + (uint32_t)sel * TILE_B + tile_off(row, u);
                CP_ASYNC16(dst, gsrc);
            }
            CP_COMMIT();
        };

        load_stage(0, 0);
        load_stage(1, 1);

        int stage = 0;
        for (int c = 0; c < NC; c++) {
            if (c + 1 < NC) { CP_WAIT(1); }
            else           { CP_WAIT(0); }
            __syncthreads();
            if (c + 2 < NC) load_stage((stage + 2) % GEMM_STAGES, c + 2);

            const uint32_t st_ = sbase + (uint32_t)stage * STAGE_B;
            const uint32_t aBase = st_;
            const uint32_t bBase = st_ + 2 * TILE_B;

#pragma unroll
            for (int kstep = 0; kstep < 2; kstep++) {
                uint32_t bh0[4], bh1[4], bl0[4], bl1[4];
                const int bunit = kstep * 2 + (q & 1);
                {
                    int brow0 = warp_n * 32 + (q >> 1) * 8 + r;
                    uint32_t a0 = bBase + tile_off(brow0, bunit);
                    LDSM_X4(bh0[0], bh0[1], bh0[2], bh0[3], a0);
                    LDSM_X4(bl0[0], bl0[1], bl0[2], bl0[3], a0 + TILE_B);
                    uint32_t a1 = bBase + tile_off(brow0 + 16, bunit);
                    LDSM_X4(bh1[0], bh1[1], bh1[2], bh1[3], a1);
                    LDSM_X4(bl1[0], bl1[1], bl1[2], bl1[3], a1 + TILE_B);
                }
                const int aunit = kstep * 2 + (q >> 1);
                const int abase_row = warp_m * 64 + (q & 1) * 8 + r;

                uint32_t ahA[4], alA[4], ahB[4], alB[4];
                {
                    uint32_t addr = aBase + tile_off(abase_row, aunit);
                    LDSM_X4(ahA[0], ahA[1], ahA[2], ahA[3], addr);
                    LDSM_X4(alA[0], alA[1], alA[2], alA[3], addr + TILE_B);
                }
#pragma unroll
                for (int mt = 0; mt < 4; mt++) {
                    uint32_t* ah = (mt & 1) ? ahB : ahA;
                    uint32_t* al = (mt & 1) ? alB : alA;
                    if (mt < 3) {
                        uint32_t* nh = (mt & 1) ? ahA : ahB;
                        uint32_t* nl = (mt & 1) ? alA : alB;
                        uint32_t addr = aBase + tile_off(abase_row + (mt + 1) * 16, aunit);
                        LDSM_X4(nh[0], nh[1], nh[2], nh[3], addr);
                        LDSM_X4(nl[0], nl[1], nl[2], nl[3], addr + TILE_B);
                    }
                    MMA_BF16(acc[mt][0], ah, bh0[0], bh0[1]);
                    MMA_BF16(acc[mt][1], ah, bh0[2], bh0[3]);
                    MMA_BF16(acc[mt][2], ah, bh1[0], bh1[1]);
                    MMA_BF16(acc[mt][3], ah, bh1[2], bh1[3]);

                    MMA_BF16(acc[mt][0], ah, bl0[0], bl0[1]);
                    MMA_BF16(acc[mt][1], ah, bl0[2], bl0[3]);
                    MMA_BF16(acc[mt][2], ah, bl1[0], bl1[1]);
                    MMA_BF16(acc[mt][3], ah, bl1[2], bl1[3]);

                    MMA_BF16(acc[mt][0], al, bh0[0], bh0[1]);
                    MMA_BF16(acc[mt][1], al, bh0[2], bh0[3]);
                    MMA_BF16(acc[mt][2], al, bh1[0], bh1[1]);
                    MMA_BF16(acc[mt][3], al, bh1[2], bh1[3]);
                }
            }
            stage = (stage + 1) % GEMM_STAGES;
        }

        // ------------------------ Epilogue ------------------------
        if (!qkv_mode) {
#pragma unroll
            for (int mt = 0; mt < 4; mt++) {
#pragma unroll
                for (int nt = 0; nt < 4; nt++) {
                    int row = m0 + warp_m * 64 + mt * 16 + gp;
                    int col = n0 + warp_n * 32 + nt * 8 + tg * 2;
                    *(float2*)&C[(size_t)row * N + col] =
                        make_float2(acc[mt][nt][0], acc[mt][nt][1]);
                    *(float2*)&C[(size_t)(row + 8) * N + col] =
                        make_float2(acc[mt][nt][2], acc[mt][nt][3]);
                }
            }
        } else if (n0 >= K_END) {
            // V tile: straight hi/lo split from registers
            int colbase = n0 - K_END;
#pragma unroll
            for (int mt = 0; mt < 4; mt++) {
#pragma unroll
                for (int nt = 0; nt < 4; nt++) {
                    int r0 = m0 + warp_m * 64 + mt * 16 + gp;
                    int cc = colbase + warp_n * 32 + nt * 8 + tg * 2;
#pragma unroll
                    for (int hf = 0; hf < 2; hf++) {
                        float o0 = acc[mt][nt][2 * hf];
                        float o1 = acc[mt][nt][2 * hf + 1];
                        float h0 = __bfloat162float(__float2bfloat16_rn(o0));
                        float h1 = __bfloat162float(__float2bfloat16_rn(o1));
                        size_t off = (size_t)(r0 + hf * 8) * KVW_ + cc;
                        *(uint32_t*)(vhi + off) = pack_bf16(h0, h1);
                        *(uint32_t*)(vlo + off) = pack_bf16(o0 - h0, o1 - h1);
                    }
                }
            }
        } else {
            // Q or K tile: stage fp32 tile to smem, rope-pair, split, store
            __syncthreads();
            float* ctile = (float*)smem;
#pragma unroll
            for (int mt = 0; mt < 4; mt++) {
#pragma unroll
                for (int nt = 0; nt < 4; nt++) {
                    int r0 = warp_m * 64 + mt * 16 + gp;
                    int cc = warp_n * 32 + nt * 8 + tg * 2;
                    ctile[r0 * CT_PITCH + cc] = acc[mt][nt][0];
                    ctile[r0 * CT_PITCH + cc + 1] = acc[mt][nt][1];
                    ctile[(r0 + 8) * CT_PITCH + cc] = acc[mt][nt][2];
                    ctile[(r0 + 8) * CT_PITCH + cc + 1] = acc[mt][nt][3];
                }
            }
            __syncthreads();

            __nv_bfloat16 *dhi, *dlo;
            int width, colbase;
            if (n0 < Q_END) { dhi = qhi; dlo = qlo; width = H_;   colbase = n0; }
            else            { dhi = khi; dlo = klo; width = KVW_; colbase = n0 - Q_END; }

#pragma unroll
            for (int it = 0; it < 16; it++) {
                int g = tid + it * 256;     // 0..4095: 128 rows x 32 pairs
                int row = g >> 5;
                int d2 = (g & 31) * 2;
                float2 x1 = *(float2*)&ctile[row * CT_PITCH + d2];
                float2 x2 = *(float2*)&ctile[row * CT_PITCH + 64 + d2];
                int s = m0 + row;
                float2 cv = *(const float2*)&ct[s * 64 + d2];
                float2 sv = *(const float2*)&st[s * 64 + d2];
                float y1a = x1.x * cv.x - x2.x * sv.x;
                float y1b = x1.y * cv.y - x2.y * sv.y;
                float y2a = x1.x * sv.x + x2.x * cv.x;
                float y2b = x1.y * sv.y + x2.y * cv.y;

                float h1a = __bfloat162float(__float2bfloat16_rn(y1a));
                float h1b = __bfloat162float(__float2bfloat16_rn(y1b));
                float h2a = __bfloat162float(__float2bfloat16_rn(y2a));
                float h2b = __bfloat162float(__float2bfloat16_rn(y2b));

                size_t ob = (size_t)s * width + colbase + d2;
                *(uint32_t*)(dhi + ob)      = pack_bf16(h1a, h1b);
                *(uint32_t*)(dlo + ob)      = pack_bf16(y1a - h1a, y1b - h1b);
                *(uint32_t*)(dhi + ob + 64) = pack_bf16(h2a, h2b);
                *(uint32_t*)(dlo + ob + 64) = pack_bf16(y2a - h2a, y2b - h2b);
            }
        }
    }
}

// ---------------------------------------------------------------------------
// Flash attention via mma.sync, bf16x3 QK^T and bf16x3 PV, causal, GQA.
// BQ=64 (4 warps), 2 CTA/SM, persistent + work-stealing, heavy-qb-first.
// SINGLE __syncthreads per kb iteration: wait(0) -> sync -> load(kb+1) ->
// compute.  At most one cp.async group in flight, so CP_WAIT(0) is exact;
// the load for kb+1 overwrites stage (kb-1)&1, whose readers all passed
// this iteration's sync.
// ---------------------------------------------------------------------------
#define AP_ 136
#define APB_ 272
#define Q_COMP_B 17408
#define KV_COMP_B 8704
#define KV_STAGE_B (4 * KV_COMP_B)
#define ATTN_SMEM_BYTES (2 * Q_COMP_B + 2 * KV_STAGE_B)   // 104448

__global__ __launch_bounds__(128, 2) void flash_attn_mma_kernel(
    const __nv_bfloat16* __restrict__ qhi, const __nv_bfloat16* __restrict__ qlo,
    const __nv_bfloat16* __restrict__ khi, const __nv_bfloat16* __restrict__ klo,
    const __nv_bfloat16* __restrict__ vhi, const __nv_bfloat16* __restrict__ vlo,
    __nv_bfloat16* __restrict__ out_hi, __nv_bfloat16* __restrict__ out_lo,
    int total_tiles, unsigned* __restrict__ counter)
{
    extern __shared__ __align__(128) char smA[];
    __shared__ unsigned s_tile;
    const uint32_t sb = smem_u32(smA);
    const int tid = threadIdx.x;
    const int wid = tid >> 5;
    const int lane = tid & 31;
    const int gp = lane >> 2;
    const int tg = lane & 3;

    const uint32_t Qhi_s = sb;
    const uint32_t Qlo_s = sb + Q_COMP_B;
    const uint32_t Stage_s = sb + 2 * Q_COMP_B;
    const float scale = 0.08838834764831845f;

    for (;;) {
        if (tid == 0) s_tile = atomicAdd(counter, 1u);
        __syncthreads();            // tile uniform + all warps done w/ prev tile
        const unsigned t = s_tile;
        if (t >= (unsigned)total_tiles) return;
        const int qb = (S_ / 64 - 1) - (int)(t >> 5);  // heavy first
        const int head = (int)(t & 31);
        const int kvh = head >> 2;
        const int q0 = qb * 64;

        // ---- load Q (one cp.async group)
#pragma unroll
        for (int i = 0; i < 16; i++) {
            int g = tid + i * 128;
            int comp = g >> 10;
            int rem = g & 1023;
            int row = rem >> 4;
            int u = rem & 15;
            const __nv_bfloat16* src = (comp ? qlo : qhi)
                + (size_t)(q0 + row) * H_ + head * HD_ + u * 8;
            uint32_t dst = (comp ? Qlo_s : Qhi_s) + (uint32_t)(row * APB_ + u * 16);
            CP_ASYNC16(dst, src);
        }
        CP_COMMIT();

        const int kb_max = 2 * qb + 1;

        auto load_kv = [&](int stage, int kb) {
            uint32_t st = Stage_s + (uint32_t)stage * KV_STAGE_B;
            const __nv_bfloat16* bases[4] = {khi, klo, vhi, vlo};
#pragma unroll
            for (int i = 0; i < 16; i++) {
                int g = tid + i * 128;
                int comp = g >> 9;
                int rem = g & 511;
                int row = rem >> 4;
                int u = rem & 15;
                const __nv_bfloat16* src = bases[comp]
                    + (size_t)(kb * 32 + row) * KVW_ + kvh * HD_ + u * 8;
                CP_ASYNC16(st + (uint32_t)(comp * KV_COMP_B + row * APB_ + u * 16), src);
            }
            CP_COMMIT();
        };

        load_kv(0, 0);

        float O[16][4];
        float m_i[2] = {-1e30f, -1e30f};
        float l_i[2] = {0.0f, 0.0f};
#pragma unroll
        for (int nt = 0; nt < 16; nt++)
#pragma unroll
            for (int e = 0; e < 4; e++) O[nt][e] = 0.0f;

        for (int kb = 0; kb <= kb_max; kb++) {
            CP_WAIT(0);             // kb's data (and Q on kb==0) landed
            __syncthreads();        // all warps done reading stage (kb-1)&1
            if (kb < kb_max) load_kv((kb + 1) & 1, kb + 1);

            const uint32_t st = Stage_s + (uint32_t)(kb & 1) * KV_STAGE_B;
            const uint32_t Ks_hi = st;
            const uint32_t Ks_lo = st + KV_COMP_B;
            const uint32_t Vs_hi = st + 2 * KV_COMP_B;
            const uint32_t Vs_lo = st + 3 * KV_COMP_B;

            float S[4][4];
#pragma unroll
            for (int tt = 0; tt < 4; tt++)
#pragma unroll
                for (int e = 0; e < 4; e++) S[tt][e] = 0.0f;

#pragma unroll
            for (int kt = 0; kt < 8; kt++) {
                uint32_t aoff = (uint32_t)((wid * 16 + (lane & 15)) * APB_
                                           + (kt * 16 + (lane >> 4) * 8) * 2);
                uint32_t ahi[4], alo[4];
                LDSM_X4(ahi[0], ahi[1], ahi[2], ahi[3], Qhi_s + aoff);
                LDSM_X4(alo[0], alo[1], alo[2], alo[3], Qlo_s + aoff);

                uint32_t bh[2][4], bl[2][4];
#pragma unroll
                for (int pr = 0; pr < 2; pr++) {
                    uint32_t boff = (uint32_t)((pr * 16 + (lane >> 4) * 8 + (lane & 7)) * APB_
                                               + (kt * 16 + ((lane >> 3) & 1) * 8) * 2);
                    LDSM_X4(bh[pr][0], bh[pr][1], bh[pr][2], bh[pr][3], Ks_hi + boff);
                    LDSM_X4(bl[pr][0], bl[pr][1], bl[pr][2], bl[pr][3], Ks_lo + boff);
                }
                MMA_BF16(S[0], ahi, bh[0][0], bh[0][1]);
                MMA_BF16(S[1], ahi, bh[0][2], bh[0][3]);
                MMA_BF16(S[2], ahi, bh[1][0], bh[1][1]);
                MMA_BF16(S[3], ahi, bh[1][2], bh[1][3]);

                MMA_BF16(S[0], ahi, bl[0][0], bl[0][1]);
                MMA_BF16(S[1], ahi, bl[0][2], bl[0][3]);
                MMA_BF16(S[2], ahi, bl[1][0], bl[1][1]);
                MMA_BF16(S[3], ahi, bl[1][2], bl[1][3]);

                MMA_BF16(S[0], alo, bh[0][0], bh[0][1]);
                MMA_BF16(S[1], alo, bh[0][2], bh[0][3]);
                MMA_BF16(S[2], alo, bh[1][0], bh[1][1]);
                MMA_BF16(S[3], alo, bh[1][2], bh[1][3]);
            }

            if (kb >= 2 * qb) {
#pragma unroll
                for (int tt = 0; tt < 4; tt++) {
                    int colb = kb * 32 + tt * 8 + 2 * tg;
#pragma unroll
                    for (int e = 0; e < 4; e++) {
                        int col = colb + (e & 1);
                        int row = q0 + wid * 16 + gp + ((e >= 2) ? 8 : 0);
                        S[tt][e] = (col <= row) ? S[tt][e] * scale : -1e30f;
                    }
                }
            } else {
#pragma unroll
                for (int tt = 0; tt < 4; tt++)
#pragma unroll
                    for (int e = 0; e < 4; e++) S[tt][e] *= scale;
            }

#pragma unroll
            for (int h = 0; h < 2; h++) {
                float mx = -1e30f;
#pragma unroll
                for (int tt = 0; tt < 4; tt++)
                    mx = fmaxf(mx, fmaxf(S[tt][2 * h], S[tt][2 * h + 1]));
                mx = fmaxf(mx, __shfl_xor_sync(0xffffffffu, mx, 1));
                mx = fmaxf(mx, __shfl_xor_sync(0xffffffffu, mx, 2));
                float m_new = fmaxf(m_i[h], mx);
                float alpha = __expf(m_i[h] - m_new);
                float sum = 0.0f;
#pragma unroll
                for (int tt = 0; tt < 4; tt++) {
                    S[tt][2 * h]     = __expf(S[tt][2 * h] - m_new);
                    S[tt][2 * h + 1] = __expf(S[tt][2 * h + 1] - m_new);
                    sum += S[tt][2 * h] + S[tt][2 * h + 1];
                }
                sum += __shfl_xor_sync(0xffffffffu, sum, 1);
                sum += __shfl_xor_sync(0xffffffffu, sum, 2);
                l_i[h] = l_i[h] * alpha + sum;
                m_i[h] = m_new;
#pragma unroll
                for (int nt = 0; nt < 16; nt++) {
                    O[nt][2 * h] *= alpha;
                    O[nt][2 * h + 1] *= alpha;
                }
            }

#pragma unroll
            for (int kt2 = 0; kt2 < 2; kt2++) {
                uint32_t phi[4], plo[4];
                {
                    float* p0 = S[2 * kt2];
                    float* p1 = S[2 * kt2 + 1];
                    float h00 = __bfloat162float(__float2bfloat16_rn(p0[0]));
                    float h01 = __bfloat162float(__float2bfloat16_rn(p0[1]));
                    float h02 = __bfloat162float(__float2bfloat16_rn(p0[2]));
                    float h03 = __bfloat162float(__float2bfloat16_rn(p0[3]));
                    float h10 = __bfloat162float(__float2bfloat16_rn(p1[0]));
                    float h11 = __bfloat162float(__float2bfloat16_rn(p1[1]));
                    float h12 = __bfloat162float(__float2bfloat16_rn(p1[2]));
                    float h13 = __bfloat162float(__float2bfloat16_rn(p1[3]));
                    phi[0] = pack_bf16(h00, h01);
                    phi[1] = pack_bf16(h02, h03);
                    phi[2] = pack_bf16(h10, h11);
                    phi[3] = pack_bf16(h12, h13);
                    plo[0] = pack_bf16(p0[0] - h00, p0[1] - h01);
                    plo[1] = pack_bf16(p0[2] - h02, p0[3] - h03);
                    plo[2] = pack_bf16(p1[0] - h10, p1[1] - h11);
                    plo[3] = pack_bf16(p1[2] - h12, p1[3] - h13);
                }
#pragma unroll
                for (int dq = 0; dq < 4; dq++) {
                    uint32_t bh0[4], bl0[4], bh1[4], bl1[4];
#pragma unroll
                    for (int half = 0; half < 2; half++) {
                        int dp = 2 * dq + half;
                        uint32_t voff = (uint32_t)((kt2 * 16 + ((lane >> 3) & 1) * 8 + (lane & 7)) * APB_
                                                   + (dp * 16 + (lane >> 4) * 8) * 2);
                        if (half == 0) {
                            LDSM_X4_T(bh0[0], bh0[1], bh0[2], bh0[3], Vs_hi + voff);
                            LDSM_X4_T(bl0[0], bl0[1], bl0[2], bl0[3], Vs_lo + voff);
                        } else {
                            LDSM_X4_T(bh1[0], bh1[1], bh1[2], bh1[3], Vs_hi + voff);
                            LDSM_X4_T(bl1[0], bl1[1], bl1[2], bl1[3], Vs_lo + voff);
                        }
                    }
                    float* O0 = O[4 * dq + 0];
                    float* O1 = O[4 * dq + 1];
                    float* O2 = O[4 * dq + 2];
                    float* O3 = O[4 * dq + 3];
                    MMA_BF16(O0, phi, bh0[0], bh0[1]);
                    MMA_BF16(O1, phi, bh0[2], bh0[3]);
                    MMA_BF16(O2, phi, bh1[0], bh1[1]);
                    MMA_BF16(O3, phi, bh1[2], bh1[3]);

                    MMA_BF16(O0, phi, bl0[0], bl0[1]);
                    MMA_BF16(O1, phi, bl0[2], bl0[3]);
                    MMA_BF16(O2, phi, bl1[0], bl1[1]);
                    MMA_BF16(O3, phi, bl1[2], bl1[3]);

                    MMA_BF16(O0, plo, bh0[0], bh0[1]);
                    MMA_BF16(O1, plo, bh0[2], bh0[3]);
                    MMA_BF16(O2, plo, bh1[0], bh1[1]);
                    MMA_BF16(O3, plo, bh1[2], bh1[3]);
                }
            }
            // no trailing sync: next iteration's load is gated by its own sync
        }

#pragma unroll
        for (int h = 0; h < 2; h++) {
            float inv = 1.0f / l_i[h];
            int row = q0 + wid * 16 + gp + h * 8;
            size_t base = (size_t)row * H_ + head * HD_;
#pragma unroll
            for (int nt = 0; nt < 16; nt++) {
                float o0 = O[nt][2 * h] * inv;
                float o1 = O[nt][2 * h + 1] * inv;
                float hh0 = __bfloat162float(__float2bfloat16_rn(o0));
                float hh1 = __bfloat162float(__float2bfloat16_rn(o1));
                size_t off = base + nt * 8 + 2 * tg;
                *(uint32_t*)(out_hi + off) = pack_bf16(hh0, hh1);
                *(uint32_t*)(out_lo + off) = pack_bf16(o0 - hh0, o1 - hh1);
            }
        }
    }
}

// ---------------------------------------------------------------------------
extern "C" void kernel_launch(void* const* d_in, const int* in_sizes, int n_in,
                              void* d_out, int out_size)
{
    const float* hidden = (const float*)d_in[0];   // [1,2048,4096]
    const float* Wqkv   = (const float*)d_in[1];   // [6144,4096]
    const float* Wo     = (const float*)d_in[2];   // [4096,4096]
    float* out = (float*)d_out;                    // [1,2048,4096]

    __nv_bfloat16 *hid_hi, *hid_lo, *wqkv_hi, *wqkv_lo, *wo_hi, *wo_lo, *attn_hi, *attn_lo;
    __nv_bfloat16 *q_hi, *q_lo, *k_hi, *k_lo, *v_hi, *v_lo;
    float *ct, *st;
    unsigned* counters;
    cudaGetSymbolAddress((void**)&hid_hi, g_hid_hi);
    cudaGetSymbolAddress((void**)&hid_lo, g_hid_lo);
    cudaGetSymbolAddress((void**)&wqkv_hi, g_wqkv_hi);
    cudaGetSymbolAddress((void**)&wqkv_lo, g_wqkv_lo);
    cudaGetSymbolAddress((void**)&wo_hi, g_wo_hi);
    cudaGetSymbolAddress((void**)&wo_lo, g_wo_lo);
    cudaGetSymbolAddress((void**)&attn_hi, g_attn_hi);
    cudaGetSymbolAddress((void**)&attn_lo, g_attn_lo);
    cudaGetSymbolAddress((void**)&q_hi, g_q_hi);
    cudaGetSymbolAddress((void**)&q_lo, g_q_lo);
    cudaGetSymbolAddress((void**)&k_hi, g_k_hi);
    cudaGetSymbolAddress((void**)&k_lo, g_k_lo);
    cudaGetSymbolAddress((void**)&v_hi, g_v_hi);
    cudaGetSymbolAddress((void**)&v_lo, g_v_lo);
    cudaGetSymbolAddress((void**)&ct, g_cos);
    cudaGetSymbolAddress((void**)&st, g_sin);
    cudaGetSymbolAddress((void**)&counters, g_counters);

    int smCount = 148;
    cudaDeviceGetAttribute(&smCount, cudaDevAttrMultiProcessorCount, 0);
    const int gemm_grid = 2 * smCount;
    const int attn_grid = 2 * smCount;

    cudaFuncSetAttribute(gemm_mma_kernel,
                         cudaFuncAttributeMaxDynamicSharedMemorySize, GEMM_SMEM_BYTES);
    cudaFuncSetAttribute(flash_attn_mma_kernel,
                         cudaFuncAttributeMaxDynamicSharedMemorySize, ATTN_SMEM_BYTES);

    // reset counters; rope tables
    cudaMemsetAsync(counters, 0, 4 * sizeof(unsigned));
    rope_table_kernel<<<S_, 64>>>(ct, st);

    // 0) fused split-convert of all inputs (single launch)
    {
        cvt_all_kernel<<<(N4_ALL + 255) / 256, 256>>>(
            hidden, Wqkv, Wo,
            hid_hi, hid_lo, wqkv_hi, wqkv_lo, wo_hi, wo_lo);
    }

    // 1) QKV projection, fused RoPE + split epilogue
    {
        int mt = S_ / 128, nt = QKV_O / 128;
        gemm_mma_kernel<<<gemm_grid, 256, GEMM_SMEM_BYTES>>>(
            hid_hi, hid_lo, wqkv_hi, wqkv_lo, nullptr, QKV_O, H_, mt, mt * nt,
            counters + 0, 1, ct, st,
            q_hi, q_lo, k_hi, k_lo, v_hi, v_lo);
    }

    // 2) Flash attention (BQ=64, 2 CTA/SM, single-sync pipeline)
    {
        int tiles = (S_ / 64) * NH_;   // 1024
        flash_attn_mma_kernel<<<attn_grid, 128, ATTN_SMEM_BYTES>>>(
            q_hi, q_lo, k_hi, k_lo, v_hi, v_lo, attn_hi, attn_lo,
            tiles, counters + 1);
    }

    // 3) Output projection (plain fp32 epilogue)
    {
        int mt = S_ / 128, nt = H_ / 128;
        gemm_mma_kernel<<<gemm_grid, 256, GEMM_SMEM_BYTES>>>(
            attn_hi, attn_lo, wo_hi, wo_lo, out, H_, H_, mt, mt * nt,
            counters + 2, 0, ct, st,
            nullptr, nullptr, nullptr, nullptr, nullptr, nullptr);
    }
}